// round 6
// baseline (speedup 1.0000x reference)
#include <cuda_runtime.h>
#include <cstdint>
#include <cstddef>

#define BB 8
#define NN 1024
#define HH 8
#define DD 64
#define CC (HH*DD)   // 512

// Scratch
__device__ float g_Wh[BB*NN*CC];
__device__ float g_hp[BB*NN*CC];
__device__ float g_s   [BB*HH*NN];
__device__ float g_t   [BB*HH*NN];
__device__ float g_es  [BB*HH*NN];
__device__ float g_es01[BB*HH*NN];
__device__ float g_et  [BB*HH*NN];
__device__ float g_et01[BB*HH*NN];
__device__ float g_was [HH*64];
__device__ float g_wat [HH*64];
// sort/scan pipeline scratch
__device__ int   g_tpi [BB*HH*NN];
__device__ float g_wA  [BB*HH*NN];
__device__ float g_wB  [BB*HH*NN];
__device__ int   g_ci  [BB*HH*NN];
__device__ int   g_qord[BB*HH*NN];
__device__ int   g_bofG[BB*HH*16];
__device__ float g_csA [BB*HH*8*64];
__device__ float g_csB [BB*HH*8*64];
__device__ float g_prA [BB*HH*8*64];
__device__ float g_prB [BB*HH*8*64];
__device__ float g_TotA[BB*HH*64];

// ---------------------------------------------------------------------------
// K0: wa[h][k] = sum_d W[k, h*64+d] * a[d]
// ---------------------------------------------------------------------------
__global__ __launch_bounds__(256) void k0_wa(const float* __restrict__ W,
                                             const float* __restrict__ a) {
    __shared__ float as[128];
    int tid = threadIdx.x;
    if (tid < 128) as[tid] = a[tid];
    __syncthreads();
    int g = blockIdx.x * 256 + tid;
    int k = g >> 3, hh = g & 7;
    const float4* w4 = (const float4*)(W + k * CC + hh * DD);
    float s = 0.f, t = 0.f;
#pragma unroll
    for (int q = 0; q < 16; q++) {
        float4 v = w4[q];
        s = fmaf(v.x, as[q*4+0], s); s = fmaf(v.y, as[q*4+1], s);
        s = fmaf(v.z, as[q*4+2], s); s = fmaf(v.w, as[q*4+3], s);
        t = fmaf(v.x, as[64+q*4+0], t); t = fmaf(v.y, as[64+q*4+1], t);
        t = fmaf(v.z, as[64+q*4+2], t); t = fmaf(v.w, as[64+q*4+3], t);
    }
    g_was[hh * 64 + k] = s;
    g_wat[hh * 64 + k] = t;
}

// ---------------------------------------------------------------------------
// K2: s,t and 4 exps per (b,n,h)
// ---------------------------------------------------------------------------
__global__ __launch_bounds__(256) void k2_vec(const float* __restrict__ hin) {
    __shared__ __align__(16) float hrow[32][68];
    __shared__ __align__(16) float was[8][64];
    __shared__ __align__(16) float wat[8][64];
    int tid = threadIdx.x;
    int n0 = blockIdx.x * 32;
    for (int idx = tid; idx < 2048; idx += 256) {
        int r = idx >> 6, k = idx & 63;
        hrow[r][k] = hin[(size_t)(n0 + r) * 64 + k];
    }
    for (int idx = tid; idx < 512; idx += 256) {
        was[idx >> 6][idx & 63] = g_was[idx];
        wat[idx >> 6][idx & 63] = g_wat[idx];
    }
    __syncthreads();
    int r = tid >> 3, hh = tid & 7;
    const float4* hv4 = (const float4*)hrow[r];
    const float4* ws4 = (const float4*)was[hh];
    const float4* wt4 = (const float4*)wat[hh];
    float s = 0.f, t = 0.f;
#pragma unroll
    for (int q = 0; q < 16; q++) {
        float4 hv = hv4[q], wv = ws4[q], tv = wt4[q];
        s = fmaf(hv.x, wv.x, s); s = fmaf(hv.y, wv.y, s);
        s = fmaf(hv.z, wv.z, s); s = fmaf(hv.w, wv.w, s);
        t = fmaf(hv.x, tv.x, t); t = fmaf(hv.y, tv.y, t);
        t = fmaf(hv.z, tv.z, t); t = fmaf(hv.w, tv.w, t);
    }
    int gr = n0 + r;
    int b = gr >> 10, n = gr & (NN - 1);
    int o = (b * HH + hh) * NN + n;
    g_s[o] = s;                   g_t[o] = t;
    g_es[o]   = __expf(s);        g_es01[o] = __expf(0.01f * s);
    g_et[o]   = __expf(t);        g_et01[o] = __expf(0.01f * t);
}

// ---------------------------------------------------------------------------
// K1: Wh = h @ W      [8192 x 64] @ [64 x 512]
// ---------------------------------------------------------------------------
__global__ __launch_bounds__(256) void k1_wh(const float* __restrict__ h,
                                             const float* __restrict__ W) {
    __shared__ __align__(16) float As[64][68];
    __shared__ __align__(16) float Bs[64][68];
    int tid = threadIdx.x;
    int r0 = blockIdx.y * 64;
    int c0 = blockIdx.x * 64;
    for (int idx = tid; idx < 4096; idx += 256) {
        int r = idx >> 6, k = idx & 63;
        As[r][k] = h[(size_t)(r0 + r) * 64 + k];
        Bs[r][k] = W[(size_t)r * CC + c0 + k];
    }
    __syncthreads();
    int tx = tid & 15, ty = tid >> 4;
    float acc[4][4] = {};
#pragma unroll
    for (int k4 = 0; k4 < 16; k4++) {
        float4 a4[4], b4[4];
#pragma unroll
        for (int r = 0; r < 4; r++) a4[r] = *(const float4*)&As[ty*4+r][k4*4];
#pragma unroll
        for (int kk = 0; kk < 4; kk++) b4[kk] = *(const float4*)&Bs[k4*4+kk][tx*4];
#pragma unroll
        for (int kk = 0; kk < 4; kk++) {
            float ak[4] = { kk==0?a4[0].x:kk==1?a4[0].y:kk==2?a4[0].z:a4[0].w,
                            kk==0?a4[1].x:kk==1?a4[1].y:kk==2?a4[1].z:a4[1].w,
                            kk==0?a4[2].x:kk==1?a4[2].y:kk==2?a4[2].z:a4[2].w,
                            kk==0?a4[3].x:kk==1?a4[3].y:kk==2?a4[3].z:a4[3].w };
            float bk[4] = { b4[kk].x, b4[kk].y, b4[kk].z, b4[kk].w };
#pragma unroll
            for (int r = 0; r < 4; r++)
#pragma unroll
                for (int c = 0; c < 4; c++)
                    acc[r][c] = fmaf(ak[r], bk[c], acc[r][c]);
        }
    }
#pragma unroll
    for (int r = 0; r < 4; r++)
#pragma unroll
        for (int c = 0; c < 4; c++)
            g_Wh[(size_t)(r0 + ty*4 + r) * CC + c0 + tx*4 + c] = acc[r][c];
}

// ---------------------------------------------------------------------------
__device__ __forceinline__ int ub1024(const float* __restrict__ arr, float key) {
    int lo = 0, hi = 1024;
    while (lo < hi) {
        int mid = (lo + hi) >> 1;
        if (arr[mid] <= key) lo = mid + 1; else hi = mid;
    }
    return lo;
}

// ---------------------------------------------------------------------------
// kA: dual bitonic sort + prefix sums + Z -> wA/wB + c_i + buckets.
// one block per (b,h), 512 threads.
// ---------------------------------------------------------------------------
__global__ __launch_bounds__(512) void kA_sort() {
    __shared__ float sv[1024];  __shared__ int sidx[1024];
    __shared__ float tv[1024];  __shared__ int tpis[1024];
    __shared__ float pes[1025], pes01[1025];
    __shared__ float aux[256], aux2[256];
    __shared__ int boff[16], cnt[16];

    int tid = threadIdx.x;
    int bh = blockIdx.x;
    int base = bh * NN;

    for (int q = tid; q < 1024; q += 512) {
        sv[q] = g_s[base + q]; sidx[q] = q;
        tv[q] = g_t[base + q]; tpis[q] = q;
    }
    if (tid < 16) { boff[tid] = 0; cnt[tid] = 0; }
    __syncthreads();

    // dual bitonic: threads 0-255 sort (sv,sidx), 256-511 sort (tv,tpis)
    {
        float* key = (tid < 256) ? sv : tv;
        int*   val = (tid < 256) ? sidx : tpis;
        int t0 = tid & 255;
        for (int k = 2; k <= 1024; k <<= 1) {
            for (int j = k >> 1; j > 0; j >>= 1) {
                __syncthreads();
#pragma unroll
                for (int rep = 0; rep < 4; rep++) {
                    int i = t0 + rep * 256;
                    int ixj = i ^ j;
                    if (ixj > i) {
                        bool up = ((i & k) == 0);
                        float a = key[i], bq = key[ixj];
                        if ((a > bq) == up) {
                            key[i] = bq; key[ixj] = a;
                            int tmp = val[i]; val[i] = val[ixj]; val[ixj] = tmp;
                        }
                    }
                }
            }
        }
    }
    __syncthreads();

    // prefix sums of es/es01 in s-sorted order (first 256 threads)
    if (tid < 256) {
        int m0 = tid * 4;
        int i0 = sidx[m0], i1 = sidx[m0+1], i2 = sidx[m0+2], i3 = sidx[m0+3];
        float x0 = g_es[base+i0], x1 = g_es[base+i1], x2 = g_es[base+i2], x3 = g_es[base+i3];
        float y0 = g_es01[base+i0], y1 = g_es01[base+i1], y2 = g_es01[base+i2], y3 = g_es01[base+i3];
        aux[tid]  = ((x0 + x1) + (x2 + x3));
        aux2[tid] = ((y0 + y1) + (y2 + y3));
        __syncthreads();
        for (int dd = 1; dd < 256; dd <<= 1) {
            float a = 0.f, a2 = 0.f;
            if (tid >= dd) { a = aux[tid - dd]; a2 = aux2[tid - dd]; }
            __syncthreads();
            aux[tid] += a; aux2[tid] += a2;
            __syncthreads();
        }
        float off  = (tid > 0) ? aux[tid - 1]  : 0.f;
        float off2 = (tid > 0) ? aux2[tid - 1] : 0.f;
        pes[m0]   = off;              pes01[m0]   = off2;
        pes[m0+1] = off + x0;         pes01[m0+1] = off2 + y0;
        pes[m0+2] = off + x0 + x1;    pes01[m0+2] = off2 + y0 + y1;
        pes[m0+3] = off + x0+x1+x2;   pes01[m0+3] = off2 + y0+y1+y2;
        if (tid == 255) {
            pes[1024]   = off  + (x0 + x1 + x2 + x3);
            pes01[1024] = off2 + (y0 + y1 + y2 + y3);
        }
    } else {
        // match barrier count of the other branch (8 rounds x 2 + 1)
        __syncthreads();
        for (int dd = 1; dd < 256; dd <<= 1) { __syncthreads(); __syncthreads(); }
    }
    __syncthreads();

    // wA/wB per sorted-t position
    {
        float ES_tot = pes[1024];
        for (int m = tid; m < 1024; m += 512) {
            int cpr = ub1024(sv, -tv[m]);
            int jo = tpis[m];
            float et = g_et[base + jo], et01 = g_et01[base + jo];
            float Z = et * (ES_tot - pes[cpr]) + et01 * pes01[cpr];
            float rz = 1.f / Z;
            g_wA[base + m] = et * rz;
            g_wB[base + m] = et01 * rz;
            g_tpi[base + m] = jo;
        }
    }

    // c_i + bucket counting
    for (int ii = tid; ii < 1024; ii += 512) {
        int c = ub1024(tv, -g_s[base + ii]);
        g_ci[base + ii] = c;
        int bu = (c == 0) ? 0 : (1 + ((c - 1) >> 7));
        atomicAdd(&boff[bu + 1], 1);
    }
    __syncthreads();
    if (tid == 0)
        for (int q = 1; q <= 9; q++) boff[q] += boff[q - 1];
    __syncthreads();
    for (int ii = tid; ii < 1024; ii += 512) {
        int c = g_ci[base + ii];
        int bu = (c == 0) ? 0 : (1 + ((c - 1) >> 7));
        int pos = boff[bu] + atomicAdd(&cnt[bu], 1);
        g_qord[base + pos] = ii;
    }
    if (tid < 16) g_bofG[bh * 16 + tid] = boff[tid];
}

// ---------------------------------------------------------------------------
// kB: chunk sums  csA/csB[bh][ch][d] = sum_{m in chunk} wX[m]*Wh[pi_m,d]
// grid 512 = bh*8+ch, 256 threads
// ---------------------------------------------------------------------------
__global__ __launch_bounds__(256) void kB_csum() {
    __shared__ float wAs[128], wBs[128];
    __shared__ int tpis[128];
    __shared__ float pA[4][64], pB[4][64];
    int tid = threadIdx.x;
    int bh = blockIdx.x >> 3, ch = blockIdx.x & 7;
    int b = bh >> 3, hh = bh & 7;
    int base = bh * NN + ch * 128;
    if (tid < 128) {
        wAs[tid] = g_wA[base + tid];
        wBs[tid] = g_wB[base + tid];
        tpis[tid] = g_tpi[base + tid];
    }
    __syncthreads();
    int g = tid >> 6, d = tid & 63;
    float pa = 0.f, pb = 0.f;
#pragma unroll 4
    for (int q = 0; q < 32; q++) {
        int m = g * 32 + q;
        float v = g_Wh[(size_t)(b * NN + tpis[m]) * CC + hh * DD + d];
        pa = fmaf(wAs[m], v, pa);
        pb = fmaf(wBs[m], v, pb);
    }
    pA[g][d] = pa; pB[g][d] = pb;
    __syncthreads();
    if (tid < 64) {
        int o = (bh * 8 + ch) * 64 + tid;
        g_csA[o] = (pA[0][tid] + pA[1][tid]) + (pA[2][tid] + pA[3][tid]);
        g_csB[o] = (pB[0][tid] + pB[1][tid]) + (pB[2][tid] + pB[3][tid]);
    }
}

// ---------------------------------------------------------------------------
// kC: coarse prefixes across 8 chunks + TotA.  64 blocks x 64 threads.
// ---------------------------------------------------------------------------
__global__ __launch_bounds__(64) void kC_pre() {
    int bh = blockIdx.x, d = threadIdx.x;
    float pa = 0.f, pb = 0.f;
#pragma unroll
    for (int ch = 0; ch < 8; ch++) {
        int o = (bh * 8 + ch) * 64 + d;
        g_prA[o] = pa; g_prB[o] = pb;
        pa += g_csA[o]; pb += g_csB[o];
    }
    g_TotA[bh * 64 + d] = pa;
}

// ---------------------------------------------------------------------------
// kD: local scan of one chunk + serve that chunk's queries.
// grid 512 = bh*8+ch, 256 threads, dynamic smem.
// ---------------------------------------------------------------------------
#define D_LOCA   0
#define D_LOCB   8192
#define D_WA     16384
#define D_WB     16512
#define D_TOT    16640
#define D_PRA    16704
#define D_PRB    16768
#define D_TPI    16832
#define KD_FLOATS 16960
#define KD_SMEM (KD_FLOATS * 4)

__global__ __launch_bounds__(256) void kD_apply() {
    extern __shared__ float sm[];
    float* locA = sm + D_LOCA;
    float* locB = sm + D_LOCB;
    float* wAs  = sm + D_WA;
    float* wBs  = sm + D_WB;
    float* Tot  = sm + D_TOT;
    float* prA  = sm + D_PRA;
    float* prB  = sm + D_PRB;
    int*   tpis = (int*)(sm + D_TPI);

    int tid = threadIdx.x;
    int bh = blockIdx.x >> 3, ch = blockIdx.x & 7;
    int b = bh >> 3, hh = bh & 7;
    int base = bh * NN;
    int cbase = base + ch * 128;

    if (tid < 128) {
        wAs[tid] = g_wA[cbase + tid];
        wBs[tid] = g_wB[cbase + tid];
        tpis[tid] = g_tpi[cbase + tid];
    } else if (tid < 192) {
        int d = tid - 128;
        Tot[d] = g_TotA[bh * 64 + d];
        prA[d] = g_prA[(bh * 8 + ch) * 64 + d];
        prB[d] = g_prB[(bh * 8 + ch) * 64 + d];
    }
    __syncthreads();

    // local scans: 128 lanes = {A,B} x 64 d
    if (tid < 128) {
        int half = tid >> 6, d = tid & 63;
        const float* w = half ? wBs : wAs;
        float* loc = half ? locB : locA;
        float run = 0.f;
#pragma unroll 4
        for (int m = 0; m < 128; m++) {
            float v = g_Wh[(size_t)(b * NN + tpis[m]) * CC + hh * DD + d];
            run = fmaf(w[m], v, run);
            loc[m * 64 + d] = run;
        }
    }
    __syncthreads();

    // queries: bucket ch+1 (c in [128ch+1, 128ch+128])
    {
        int qs = g_bofG[bh * 16 + ch + 1];
        int qe = g_bofG[bh * 16 + ch + 2];
        int qg = tid >> 6, d = tid & 63;
        for (int q = qs + qg; q < qe; q += 4) {
            int i = g_qord[base + q];
            int off = g_ci[base + i] - ch * 128 - 1;
            float es = g_es[base + i], es01 = g_es01[base + i];
            float val = es * (Tot[d] - prA[d] - locA[off * 64 + d])
                      + es01 * (prB[d] + locB[off * 64 + d]);
            g_hp[(size_t)(b * NN + i) * CC + hh * DD + d] = val;
        }
        // bucket 0 (c = 0): h' = es_i * TotA, handled by ch==0 block
        if (ch == 0) {
            int q0 = g_bofG[bh * 16 + 0];
            int q1 = g_bofG[bh * 16 + 1];
            for (int q = q0 + qg; q < q1; q += 4) {
                int i = g_qord[base + q];
                float es = g_es[base + i];
                g_hp[(size_t)(b * NN + i) * CC + hh * DD + d] = es * Tot[d];
            }
        }
    }
}

// ---------------------------------------------------------------------------
// K5: out = h_prime @ out_W + out_b    [8192 x 512] @ [512 x 64]
// ---------------------------------------------------------------------------
__global__ __launch_bounds__(256) void k5_out(const float* __restrict__ oW,
                                              const float* __restrict__ ob,
                                              float* __restrict__ out) {
    __shared__ __align__(16) float As[64][68];
    __shared__ __align__(16) float Bs[64][68];
    int tid = threadIdx.x;
    int r0 = blockIdx.x * 64;
    int tx = tid & 15, ty = tid >> 4;
    float acc[4][4] = {};
    for (int kt = 0; kt < CC; kt += 64) {
        __syncthreads();
        for (int idx = tid; idx < 4096; idx += 256) {
            int r = idx >> 6, k = idx & 63;
            As[r][k] = g_hp[(size_t)(r0 + r) * CC + kt + k];
            Bs[r][k] = oW[(size_t)(kt + r) * DD + k];
        }
        __syncthreads();
#pragma unroll
        for (int k4 = 0; k4 < 16; k4++) {
            float4 a4[4], b4[4];
#pragma unroll
            for (int r = 0; r < 4; r++) a4[r] = *(const float4*)&As[ty*4+r][k4*4];
#pragma unroll
            for (int kk = 0; kk < 4; kk++) b4[kk] = *(const float4*)&Bs[k4*4+kk][tx*4];
#pragma unroll
            for (int kk = 0; kk < 4; kk++) {
                float ak[4] = { kk==0?a4[0].x:kk==1?a4[0].y:kk==2?a4[0].z:a4[0].w,
                                kk==0?a4[1].x:kk==1?a4[1].y:kk==2?a4[1].z:a4[1].w,
                                kk==0?a4[2].x:kk==1?a4[2].y:kk==2?a4[2].z:a4[2].w,
                                kk==0?a4[3].x:kk==1?a4[3].y:kk==2?a4[3].z:a4[3].w };
                float bk[4] = { b4[kk].x, b4[kk].y, b4[kk].z, b4[kk].w };
#pragma unroll
                for (int r = 0; r < 4; r++)
#pragma unroll
                    for (int c = 0; c < 4; c++)
                        acc[r][c] = fmaf(ak[r], bk[c], acc[r][c]);
            }
        }
    }
#pragma unroll
    for (int r = 0; r < 4; r++)
#pragma unroll
        for (int c = 0; c < 4; c++)
            out[(size_t)(r0 + ty*4 + r) * DD + tx*4 + c] = acc[r][c] + ob[tx*4+c];
}

// ---------------------------------------------------------------------------
extern "C" void kernel_launch(void* const* d_in, const int* in_sizes, int n_in,
                              void* d_out, int out_size) {
    const float* h    = (const float*)d_in[0];
    const float* W    = (const float*)d_in[2];
    const float* a    = (const float*)d_in[3];
    const float* oW   = (const float*)d_in[4];
    const float* ob   = (const float*)d_in[5];
    float* out = (float*)d_out;

    cudaFuncSetAttribute(kD_apply, cudaFuncAttributeMaxDynamicSharedMemorySize,
                         KD_SMEM);

    k0_wa <<<2, 256>>>(W, a);
    k2_vec<<<(BB*NN)/32, 256>>>(h);
    k1_wh <<<dim3(CC/64, (BB*NN)/64), 256>>>(h, W);
    kA_sort<<<BB*HH, 512>>>();
    kB_csum<<<BB*HH*8, 256>>>();
    kC_pre <<<BB*HH, 64>>>();
    kD_apply<<<BB*HH*8, 256, KD_SMEM>>>();
    k5_out<<<(BB*NN)/64, 256>>>(oW, ob, out);
}

// round 7
// speedup vs baseline: 1.0940x; 1.0940x over previous
#include <cuda_runtime.h>
#include <cstdint>
#include <cstddef>

#define BB 8
#define NN 1024
#define HH 8
#define DD 64
#define CC (HH*DD)   // 512

// Scratch
__device__ float g_Wh[BB*NN*CC];
__device__ float g_hp[BB*NN*CC];
__device__ float g_s   [BB*HH*NN];
__device__ float g_t   [BB*HH*NN];
__device__ float g_es  [BB*HH*NN];
__device__ float g_es01[BB*HH*NN];
__device__ float g_et  [BB*HH*NN];
__device__ float g_et01[BB*HH*NN];
// sort/scan pipeline scratch
__device__ int   g_tpi [BB*HH*NN];
__device__ float g_wA  [BB*HH*NN];
__device__ float g_wB  [BB*HH*NN];
__device__ int   g_ci  [BB*HH*NN];
__device__ int   g_qord[BB*HH*NN];
__device__ int   g_bofG[BB*HH*16];
__device__ float g_prA [BB*HH*8*64];
__device__ float g_prB [BB*HH*8*64];
__device__ float g_TotA[BB*HH*64];

// ---------------------------------------------------------------------------
// k1x: Wh = h @ W  (one 64-row x one-head tile per block), fused with
//      s_i = Wh[i,h,:].a[:64], t_i = Wh[i,h,:].a[64:], and the 4 exps.
// grid (8 heads, 128 row-tiles), 256 threads.
// ---------------------------------------------------------------------------
__global__ __launch_bounds__(256) void k1x(const float* __restrict__ h,
                                           const float* __restrict__ W,
                                           const float* __restrict__ a) {
    __shared__ __align__(16) float As[64][68];   // [row][k]
    __shared__ __align__(16) float Bs[64][68];   // [k][col]
    __shared__ float as[128];
    __shared__ float sred[64][17], tred[64][17];
    int tid = threadIdx.x;
    int hh = blockIdx.x;
    int r0 = blockIdx.y * 64;
    int c0 = hh * 64;
    if (tid < 128) as[tid] = a[tid];
    for (int idx = tid; idx < 4096; idx += 256) {
        int r = idx >> 6, k = idx & 63;
        As[r][k] = h[(size_t)(r0 + r) * 64 + k];
        Bs[r][k] = W[(size_t)r * CC + c0 + k];
    }
    __syncthreads();
    int tx = tid & 15, ty = tid >> 4;
    float acc[4][4] = {};
#pragma unroll
    for (int k4 = 0; k4 < 16; k4++) {
        float4 a4[4], b4[4];
#pragma unroll
        for (int r = 0; r < 4; r++) a4[r] = *(const float4*)&As[ty*4+r][k4*4];
#pragma unroll
        for (int kk = 0; kk < 4; kk++) b4[kk] = *(const float4*)&Bs[k4*4+kk][tx*4];
#pragma unroll
        for (int kk = 0; kk < 4; kk++) {
            float ak[4] = { kk==0?a4[0].x:kk==1?a4[0].y:kk==2?a4[0].z:a4[0].w,
                            kk==0?a4[1].x:kk==1?a4[1].y:kk==2?a4[1].z:a4[1].w,
                            kk==0?a4[2].x:kk==1?a4[2].y:kk==2?a4[2].z:a4[2].w,
                            kk==0?a4[3].x:kk==1?a4[3].y:kk==2?a4[3].z:a4[3].w };
            float bk[4] = { b4[kk].x, b4[kk].y, b4[kk].z, b4[kk].w };
#pragma unroll
            for (int r = 0; r < 4; r++)
#pragma unroll
                for (int c = 0; c < 4; c++)
                    acc[r][c] = fmaf(ak[r], bk[c], acc[r][c]);
        }
    }
#pragma unroll
    for (int r = 0; r < 4; r++) {
#pragma unroll
        for (int c = 0; c < 4; c++)
            g_Wh[(size_t)(r0 + ty*4 + r) * CC + c0 + tx*4 + c] = acc[r][c];
        // s/t partials: dot of this thread's 4 cols with a (within-head d)
        float ps = 0.f, pt = 0.f;
#pragma unroll
        for (int c = 0; c < 4; c++) {
            ps = fmaf(acc[r][c], as[tx*4 + c], ps);
            pt = fmaf(acc[r][c], as[64 + tx*4 + c], pt);
        }
        sred[ty*4 + r][tx] = ps;
        tred[ty*4 + r][tx] = pt;
    }
    __syncthreads();
    if (tid < 64) {
        float s = 0.f, t = 0.f;
#pragma unroll
        for (int x = 0; x < 16; x++) { s += sred[tid][x]; t += tred[tid][x]; }
        int gr = r0 + tid;
        int b = gr >> 10, n = gr & (NN - 1);
        int o = (b * HH + hh) * NN + n;
        g_s[o] = s;                 g_t[o] = t;
        g_es[o]   = __expf(s);      g_es01[o] = __expf(0.01f * s);
        g_et[o]   = __expf(t);      g_et01[o] = __expf(0.01f * t);
    }
}

// ---------------------------------------------------------------------------
__device__ __forceinline__ int ub1024(const float* __restrict__ arr, float key) {
    int lo = 0, hi = 1024;
    while (lo < hi) {
        int mid = (lo + hi) >> 1;
        if (arr[mid] <= key) lo = mid + 1; else hi = mid;
    }
    return lo;
}

// ---------------------------------------------------------------------------
// kS: one block per (b,h), 1024 threads (one per element).
//   dual bitonic sort (s and t, same thread handles both), Hillis-Steele
//   prefix scans of es/es01 in s-sorted order, Z -> wA/wB, c_i, buckets,
//   chunk sums + coarse prefixes + TotA.
// ---------------------------------------------------------------------------
// dynamic smem offsets (floats)
#define S_SV    0
#define S_TV    1024
#define S_SIDX  2048
#define S_TPI   3072
#define S_SCANA 4096    /* 2 x 1024 ping-pong */
#define S_SCANB 6144    /* 2 x 1024 */
#define S_WAS   8192
#define S_WBS   9216
#define S_PARTA 10240   /* [8][2][64] */
#define S_PARTB 11264
#define S_BOFF  12288   /* 16 ints */
#define S_CNT   12304   /* 16 ints */
#define KS_FLOATS 12320
#define KS_SMEM (KS_FLOATS * 4)

__global__ __launch_bounds__(1024) void kS_all() {
    extern __shared__ float sm[];
    float* sv    = sm + S_SV;
    float* tv    = sm + S_TV;
    int*   sidx  = (int*)(sm + S_SIDX);
    int*   tpi   = (int*)(sm + S_TPI);
    float* scanA = sm + S_SCANA;
    float* scanB = sm + S_SCANB;
    float* wAs   = sm + S_WAS;
    float* wBs   = sm + S_WBS;
    float* partA = sm + S_PARTA;
    float* partB = sm + S_PARTB;
    int*   boff  = (int*)(sm + S_BOFF);
    int*   cnt   = (int*)(sm + S_CNT);

    int tid = threadIdx.x;
    int bh = blockIdx.x;
    int b = bh >> 3, hh = bh & 7;
    int base = bh * NN;

    float s0 = g_s[base + tid];
    sv[tid] = s0;  sidx[tid] = tid;
    tv[tid] = g_t[base + tid];  tpi[tid] = tid;
    if (tid < 16) { boff[tid] = 0; cnt[tid] = 0; }
    __syncthreads();

    // dual bitonic sort, one element per thread
    for (int k = 2; k <= 1024; k <<= 1) {
        for (int j = k >> 1; j > 0; j >>= 1) {
            int ixj = tid ^ j;
            if (ixj > tid) {
                bool up = ((tid & k) == 0);
                float av = sv[tid], bv = sv[ixj];
                if ((av > bv) == up) {
                    sv[tid] = bv; sv[ixj] = av;
                    int tmp = sidx[tid]; sidx[tid] = sidx[ixj]; sidx[ixj] = tmp;
                }
                float at = tv[tid], bt = tv[ixj];
                if ((at > bt) == up) {
                    tv[tid] = bt; tv[ixj] = at;
                    int tmp = tpi[tid]; tpi[tid] = tpi[ixj]; tpi[ixj] = tmp;
                }
            }
            __syncthreads();
        }
    }

    // inclusive scans of es/es01 gathered in s-sorted order
    {
        int io = sidx[tid];
        scanA[tid] = g_es[base + io];
        scanB[tid] = g_es01[base + io];
    }
    __syncthreads();
    int src = 0;
    for (int d = 1; d < 1024; d <<= 1) {
        float aA = scanA[src*1024 + tid], aB = scanB[src*1024 + tid];
        if (tid >= d) {
            aA += scanA[src*1024 + tid - d];
            aB += scanB[src*1024 + tid - d];
        }
        scanA[(1 - src)*1024 + tid] = aA;
        scanB[(1 - src)*1024 + tid] = aB;
        __syncthreads();
        src ^= 1;
    }
    const float* inclA = scanA + src * 1024;
    const float* inclB = scanB + src * 1024;
    float ES_tot = inclA[1023];

    // Z at sorted-t position tid -> wA/wB
    {
        int cpr = ub1024(sv, -tv[tid]);
        int jo = tpi[tid];
        float et = g_et[base + jo], et01 = g_et01[base + jo];
        float pa = cpr ? inclA[cpr - 1] : 0.f;
        float pb = cpr ? inclB[cpr - 1] : 0.f;
        float rz = 1.f / (et * (ES_tot - pa) + et01 * pb);
        float wa = et * rz, wb = et01 * rz;
        wAs[tid] = wa;  wBs[tid] = wb;
        g_wA[base + tid] = wa;
        g_wB[base + tid] = wb;
        g_tpi[base + tid] = jo;
    }

    // c_i + bucket count (i = tid, original s in s0)
    {
        int c = ub1024(tv, -s0);
        g_ci[base + tid] = c;
        int bu = (c == 0) ? 0 : (1 + ((c - 1) >> 7));
        atomicAdd(&boff[bu + 1], 1);
    }
    __syncthreads();   // wAs/wBs + counts complete

    // chunk partial sums: thread = (ch, mh, d)
    {
        int ch = tid >> 7;
        int mh = (tid >> 6) & 1;
        int d = tid & 63;
        int m0 = ch * 128 + mh * 64;
        float pa = 0.f, pb = 0.f;
#pragma unroll 4
        for (int q = 0; q < 64; q++) {
            int m = m0 + q;
            float v = g_Wh[(size_t)(b * NN + tpi[m]) * CC + hh * DD + d];
            pa = fmaf(wAs[m], v, pa);
            pb = fmaf(wBs[m], v, pb);
        }
        partA[(ch * 2 + mh) * 64 + d] = pa;
        partB[(ch * 2 + mh) * 64 + d] = pb;
    }
    __syncthreads();

    if (tid == 0)
        for (int q = 1; q <= 9; q++) boff[q] += boff[q - 1];
    __syncthreads();

    // qord scatter
    {
        int c = g_ci[base + tid];
        int bu = (c == 0) ? 0 : (1 + ((c - 1) >> 7));
        int pos = boff[bu] + atomicAdd(&cnt[bu], 1);
        g_qord[base + pos] = tid;
    }
    if (tid < 16) g_bofG[bh * 16 + tid] = boff[tid];

    // coarse prefixes + TotA
    if (tid < 64) {
        int d = tid;
        float pa = 0.f, pb = 0.f;
#pragma unroll
        for (int ch = 0; ch < 8; ch++) {
            int o = (bh * 8 + ch) * 64 + d;
            g_prA[o] = pa;  g_prB[o] = pb;
            pa += partA[(ch * 2) * 64 + d] + partA[(ch * 2 + 1) * 64 + d];
            pb += partB[(ch * 2) * 64 + d] + partB[(ch * 2 + 1) * 64 + d];
        }
        g_TotA[bh * 64 + d] = pa;
    }
}

// ---------------------------------------------------------------------------
// kD: local scan of one chunk + serve that chunk's queries.
// grid 512 = bh*8+ch, 256 threads, dynamic smem.
// ---------------------------------------------------------------------------
#define D_LOCA   0
#define D_LOCB   8192
#define D_WA     16384
#define D_WB     16512
#define D_TOT    16640
#define D_PRA    16704
#define D_PRB    16768
#define D_TPI    16832
#define KD_FLOATS 16960
#define KD_SMEM (KD_FLOATS * 4)

__global__ __launch_bounds__(256) void kD_apply() {
    extern __shared__ float sm[];
    float* locA = sm + D_LOCA;
    float* locB = sm + D_LOCB;
    float* wAs  = sm + D_WA;
    float* wBs  = sm + D_WB;
    float* Tot  = sm + D_TOT;
    float* prA  = sm + D_PRA;
    float* prB  = sm + D_PRB;
    int*   tpis = (int*)(sm + D_TPI);

    int tid = threadIdx.x;
    int bh = blockIdx.x >> 3, ch = blockIdx.x & 7;
    int b = bh >> 3, hh = bh & 7;
    int base = bh * NN;
    int cbase = base + ch * 128;

    if (tid < 128) {
        wAs[tid] = g_wA[cbase + tid];
        wBs[tid] = g_wB[cbase + tid];
        tpis[tid] = g_tpi[cbase + tid];
    } else if (tid < 192) {
        int d = tid - 128;
        Tot[d] = g_TotA[bh * 64 + d];
        prA[d] = g_prA[(bh * 8 + ch) * 64 + d];
        prB[d] = g_prB[(bh * 8 + ch) * 64 + d];
    }
    __syncthreads();

    if (tid < 128) {
        int half = tid >> 6, d = tid & 63;
        const float* w = half ? wBs : wAs;
        float* loc = half ? locB : locA;
        float run = 0.f;
#pragma unroll 4
        for (int m = 0; m < 128; m++) {
            float v = g_Wh[(size_t)(b * NN + tpis[m]) * CC + hh * DD + d];
            run = fmaf(w[m], v, run);
            loc[m * 64 + d] = run;
        }
    }
    __syncthreads();

    {
        int qs = g_bofG[bh * 16 + ch + 1];
        int qe = g_bofG[bh * 16 + ch + 2];
        int qg = tid >> 6, d = tid & 63;
        for (int q = qs + qg; q < qe; q += 4) {
            int i = g_qord[base + q];
            int off = g_ci[base + i] - ch * 128 - 1;
            float es = g_es[base + i], es01 = g_es01[base + i];
            float val = es * (Tot[d] - prA[d] - locA[off * 64 + d])
                      + es01 * (prB[d] + locB[off * 64 + d]);
            g_hp[(size_t)(b * NN + i) * CC + hh * DD + d] = val;
        }
        if (ch == 0) {
            int q0 = g_bofG[bh * 16 + 0];
            int q1 = g_bofG[bh * 16 + 1];
            for (int q = q0 + qg; q < q1; q += 4) {
                int i = g_qord[base + q];
                float es = g_es[base + i];
                g_hp[(size_t)(b * NN + i) * CC + hh * DD + d] = es * Tot[d];
            }
        }
    }
}

// ---------------------------------------------------------------------------
// K5: out = h_prime @ out_W + out_b    [8192 x 512] @ [512 x 64]
// ---------------------------------------------------------------------------
__global__ __launch_bounds__(256) void k5_out(const float* __restrict__ oW,
                                              const float* __restrict__ ob,
                                              float* __restrict__ out) {
    __shared__ __align__(16) float As[64][68];
    __shared__ __align__(16) float Bs[64][68];
    int tid = threadIdx.x;
    int r0 = blockIdx.x * 64;
    int tx = tid & 15, ty = tid >> 4;
    float acc[4][4] = {};
    for (int kt = 0; kt < CC; kt += 64) {
        __syncthreads();
        for (int idx = tid; idx < 4096; idx += 256) {
            int r = idx >> 6, k = idx & 63;
            As[r][k] = g_hp[(size_t)(r0 + r) * CC + kt + k];
            Bs[r][k] = oW[(size_t)(kt + r) * DD + k];
        }
        __syncthreads();
#pragma unroll
        for (int k4 = 0; k4 < 16; k4++) {
            float4 a4[4], b4[4];
#pragma unroll
            for (int r = 0; r < 4; r++) a4[r] = *(const float4*)&As[ty*4+r][k4*4];
#pragma unroll
            for (int kk = 0; kk < 4; kk++) b4[kk] = *(const float4*)&Bs[k4*4+kk][tx*4];
#pragma unroll
            for (int kk = 0; kk < 4; kk++) {
                float ak[4] = { kk==0?a4[0].x:kk==1?a4[0].y:kk==2?a4[0].z:a4[0].w,
                                kk==0?a4[1].x:kk==1?a4[1].y:kk==2?a4[1].z:a4[1].w,
                                kk==0?a4[2].x:kk==1?a4[2].y:kk==2?a4[2].z:a4[2].w,
                                kk==0?a4[3].x:kk==1?a4[3].y:kk==2?a4[3].z:a4[3].w };
                float bk[4] = { b4[kk].x, b4[kk].y, b4[kk].z, b4[kk].w };
#pragma unroll
                for (int r = 0; r < 4; r++)
#pragma unroll
                    for (int c = 0; c < 4; c++)
                        acc[r][c] = fmaf(ak[r], bk[c], acc[r][c]);
            }
        }
    }
#pragma unroll
    for (int r = 0; r < 4; r++)
#pragma unroll
        for (int c = 0; c < 4; c++)
            out[(size_t)(r0 + ty*4 + r) * DD + tx*4 + c] = acc[r][c] + ob[tx*4+c];
}

// ---------------------------------------------------------------------------
extern "C" void kernel_launch(void* const* d_in, const int* in_sizes, int n_in,
                              void* d_out, int out_size) {
    const float* h    = (const float*)d_in[0];
    const float* W    = (const float*)d_in[2];
    const float* a    = (const float*)d_in[3];
    const float* oW   = (const float*)d_in[4];
    const float* ob   = (const float*)d_in[5];
    float* out = (float*)d_out;

    cudaFuncSetAttribute(kS_all, cudaFuncAttributeMaxDynamicSharedMemorySize,
                         KS_SMEM);
    cudaFuncSetAttribute(kD_apply, cudaFuncAttributeMaxDynamicSharedMemorySize,
                         KD_SMEM);

    k1x<<<dim3(HH, (BB*NN)/64), 256>>>(h, W, a);
    kS_all<<<BB*HH, 1024, KS_SMEM>>>();
    kD_apply<<<BB*HH*8, 256, KD_SMEM>>>();
    k5_out<<<(BB*NN)/64, 256>>>(oW, ob, out);
}

// round 8
// speedup vs baseline: 1.6445x; 1.5032x over previous
#include <cuda_runtime.h>
#include <cstdint>
#include <cstddef>

#define BB 8
#define NN 1024
#define HH 8
#define DD 64
#define CC (HH*DD)   // 512

// Scratch
__device__ float g_Wh[BB*NN*CC];
__device__ float g_hp[BB*NN*CC];
__device__ float g_s   [BB*HH*NN];
__device__ float g_t   [BB*HH*NN];
__device__ float g_es  [BB*HH*NN];
__device__ float g_es01[BB*HH*NN];
__device__ float g_et  [BB*HH*NN];
__device__ float g_et01[BB*HH*NN];
// sort/scan pipeline scratch
__device__ int   g_tpi [BB*HH*NN];
__device__ float g_wA  [BB*HH*NN];
__device__ float g_wB  [BB*HH*NN];
__device__ int   g_ci  [BB*HH*NN];
__device__ int   g_qord[BB*HH*NN];
__device__ int   g_bofG[BB*HH*16];
__device__ float g_prA [BB*HH*8*64];
__device__ float g_prB [BB*HH*8*64];
__device__ float g_TotA[BB*HH*64];

// ---------------------------------------------------------------------------
// k1x: Wh = h @ W (64-row x one-head tile per block) fused with s/t/exp.
// grid (8 heads, 128 row-tiles), 256 threads. All global loads float4.
// ---------------------------------------------------------------------------
__global__ __launch_bounds__(256) void k1x(const float* __restrict__ h,
                                           const float* __restrict__ W,
                                           const float* __restrict__ a) {
    __shared__ __align__(16) float As[64][68];   // [row][k]
    __shared__ __align__(16) float Bs[64][68];   // [k][col]
    __shared__ float as[128];
    __shared__ float sred[64][17], tred[64][17];
    int tid = threadIdx.x;
    int hh = blockIdx.x;
    int r0 = blockIdx.y * 64;
    int c0 = hh * 64;
    if (tid < 128) as[tid] = a[tid];
#pragma unroll
    for (int p = 0; p < 4; p++) {
        int idx = p * 256 + tid;          // 0..1023
        int r = idx >> 4, k4 = idx & 15;
        *(float4*)&As[r][k4*4] = *(const float4*)&h[(size_t)(r0 + r) * 64 + k4*4];
        *(float4*)&Bs[r][k4*4] = *(const float4*)&W[(size_t)r * CC + c0 + k4*4];
    }
    __syncthreads();
    int tx = tid & 15, ty = tid >> 4;
    float acc[4][4] = {};
#pragma unroll
    for (int k4 = 0; k4 < 16; k4++) {
        float4 a4[4], b4[4];
#pragma unroll
        for (int r = 0; r < 4; r++) a4[r] = *(const float4*)&As[ty*4+r][k4*4];
#pragma unroll
        for (int kk = 0; kk < 4; kk++) b4[kk] = *(const float4*)&Bs[k4*4+kk][tx*4];
#pragma unroll
        for (int kk = 0; kk < 4; kk++) {
            float ak[4] = { kk==0?a4[0].x:kk==1?a4[0].y:kk==2?a4[0].z:a4[0].w,
                            kk==0?a4[1].x:kk==1?a4[1].y:kk==2?a4[1].z:a4[1].w,
                            kk==0?a4[2].x:kk==1?a4[2].y:kk==2?a4[2].z:a4[2].w,
                            kk==0?a4[3].x:kk==1?a4[3].y:kk==2?a4[3].z:a4[3].w };
            float bk[4] = { b4[kk].x, b4[kk].y, b4[kk].z, b4[kk].w };
#pragma unroll
            for (int r = 0; r < 4; r++)
#pragma unroll
                for (int c = 0; c < 4; c++)
                    acc[r][c] = fmaf(ak[r], bk[c], acc[r][c]);
        }
    }
#pragma unroll
    for (int r = 0; r < 4; r++) {
        float4 o = {acc[r][0], acc[r][1], acc[r][2], acc[r][3]};
        *(float4*)&g_Wh[(size_t)(r0 + ty*4 + r) * CC + c0 + tx*4] = o;
        float ps = 0.f, pt = 0.f;
#pragma unroll
        for (int c = 0; c < 4; c++) {
            ps = fmaf(acc[r][c], as[tx*4 + c], ps);
            pt = fmaf(acc[r][c], as[64 + tx*4 + c], pt);
        }
        sred[ty*4 + r][tx] = ps;
        tred[ty*4 + r][tx] = pt;
    }
    __syncthreads();
    if (tid < 64) {
        float s = 0.f, t = 0.f;
#pragma unroll
        for (int x = 0; x < 16; x++) { s += sred[tid][x]; t += tred[tid][x]; }
        int gr = r0 + tid;
        int b = gr >> 10, n = gr & (NN - 1);
        int o = (b * HH + hh) * NN + n;
        g_s[o] = s;                 g_t[o] = t;
        g_es[o]   = __expf(s);      g_es01[o] = __expf(0.01f * s);
        g_et[o]   = __expf(t);      g_et01[o] = __expf(0.01f * t);
    }
}

// ---------------------------------------------------------------------------
__device__ __forceinline__ int ub1024(const float* __restrict__ arr, float key) {
    int lo = 0, hi = 1024;
    while (lo < hi) {
        int mid = (lo + hi) >> 1;
        if (arr[mid] <= key) lo = mid + 1; else hi = mid;
    }
    return lo;
}

// ---------------------------------------------------------------------------
// kS: one block per (b,h), 1024 threads. Sorts, scans, Z, buckets, coarse sums.
// ---------------------------------------------------------------------------
#define S_SV    0
#define S_TV    1024
#define S_SIDX  2048
#define S_TPI   3072
#define S_SCANA 4096    /* 2 x 1024 ping-pong */
#define S_SCANB 6144    /* 2 x 1024 */
#define S_WAS   8192
#define S_WBS   9216
#define S_PARTA 10240   /* [8][2][64] */
#define S_PARTB 11264
#define S_BOFF  12288
#define S_CNT   12304
#define KS_FLOATS 12320
#define KS_SMEM (KS_FLOATS * 4)

__global__ __launch_bounds__(1024) void kS_all() {
    extern __shared__ float sm[];
    float* sv    = sm + S_SV;
    float* tv    = sm + S_TV;
    int*   sidx  = (int*)(sm + S_SIDX);
    int*   tpi   = (int*)(sm + S_TPI);
    float* scanA = sm + S_SCANA;
    float* scanB = sm + S_SCANB;
    float* wAs   = sm + S_WAS;
    float* wBs   = sm + S_WBS;
    float* partA = sm + S_PARTA;
    float* partB = sm + S_PARTB;
    int*   boff  = (int*)(sm + S_BOFF);
    int*   cnt   = (int*)(sm + S_CNT);

    int tid = threadIdx.x;
    int bh = blockIdx.x;
    int b = bh >> 3, hh = bh & 7;
    int base = bh * NN;

    float s0 = g_s[base + tid];
    sv[tid] = s0;  sidx[tid] = tid;
    tv[tid] = g_t[base + tid];  tpi[tid] = tid;
    if (tid < 16) { boff[tid] = 0; cnt[tid] = 0; }
    __syncthreads();

    for (int k = 2; k <= 1024; k <<= 1) {
        for (int j = k >> 1; j > 0; j >>= 1) {
            int ixj = tid ^ j;
            if (ixj > tid) {
                bool up = ((tid & k) == 0);
                float av = sv[tid], bv = sv[ixj];
                if ((av > bv) == up) {
                    sv[tid] = bv; sv[ixj] = av;
                    int tmp = sidx[tid]; sidx[tid] = sidx[ixj]; sidx[ixj] = tmp;
                }
                float at = tv[tid], bt = tv[ixj];
                if ((at > bt) == up) {
                    tv[tid] = bt; tv[ixj] = at;
                    int tmp = tpi[tid]; tpi[tid] = tpi[ixj]; tpi[ixj] = tmp;
                }
            }
            __syncthreads();
        }
    }

    {
        int io = sidx[tid];
        scanA[tid] = g_es[base + io];
        scanB[tid] = g_es01[base + io];
    }
    __syncthreads();
    int src = 0;
    for (int d = 1; d < 1024; d <<= 1) {
        float aA = scanA[src*1024 + tid], aB = scanB[src*1024 + tid];
        if (tid >= d) {
            aA += scanA[src*1024 + tid - d];
            aB += scanB[src*1024 + tid - d];
        }
        scanA[(1 - src)*1024 + tid] = aA;
        scanB[(1 - src)*1024 + tid] = aB;
        __syncthreads();
        src ^= 1;
    }
    const float* inclA = scanA + src * 1024;
    const float* inclB = scanB + src * 1024;
    float ES_tot = inclA[1023];

    {
        int cpr = ub1024(sv, -tv[tid]);
        int jo = tpi[tid];
        float et = g_et[base + jo], et01 = g_et01[base + jo];
        float pa = cpr ? inclA[cpr - 1] : 0.f;
        float pb = cpr ? inclB[cpr - 1] : 0.f;
        float rz = 1.f / (et * (ES_tot - pa) + et01 * pb);
        float wa = et * rz, wb = et01 * rz;
        wAs[tid] = wa;  wBs[tid] = wb;
        g_wA[base + tid] = wa;
        g_wB[base + tid] = wb;
        g_tpi[base + tid] = jo;
    }

    {
        int c = ub1024(tv, -s0);
        g_ci[base + tid] = c;
        int bu = (c == 0) ? 0 : (1 + ((c - 1) >> 7));
        atomicAdd(&boff[bu + 1], 1);
    }
    __syncthreads();

    {
        int ch = tid >> 7;
        int mh = (tid >> 6) & 1;
        int d = tid & 63;
        int m0 = ch * 128 + mh * 64;
        float pa = 0.f, pb = 0.f;
#pragma unroll 4
        for (int q = 0; q < 64; q++) {
            int m = m0 + q;
            float v = g_Wh[(size_t)(b * NN + tpi[m]) * CC + hh * DD + d];
            pa = fmaf(wAs[m], v, pa);
            pb = fmaf(wBs[m], v, pb);
        }
        partA[(ch * 2 + mh) * 64 + d] = pa;
        partB[(ch * 2 + mh) * 64 + d] = pb;
    }
    __syncthreads();

    if (tid == 0)
        for (int q = 1; q <= 9; q++) boff[q] += boff[q - 1];
    __syncthreads();

    {
        int c = g_ci[base + tid];
        int bu = (c == 0) ? 0 : (1 + ((c - 1) >> 7));
        int pos = boff[bu] + atomicAdd(&cnt[bu], 1);
        g_qord[base + pos] = tid;
    }
    if (tid < 16) g_bofG[bh * 16 + tid] = boff[tid];

    if (tid < 64) {
        int d = tid;
        float pa = 0.f, pb = 0.f;
#pragma unroll
        for (int ch = 0; ch < 8; ch++) {
            int o = (bh * 8 + ch) * 64 + d;
            g_prA[o] = pa;  g_prB[o] = pb;
            pa += partA[(ch * 2) * 64 + d] + partA[(ch * 2 + 1) * 64 + d];
            pb += partB[(ch * 2) * 64 + d] + partB[(ch * 2 + 1) * 64 + d];
        }
        g_TotA[bh * 64 + d] = pa;
    }
}

// ---------------------------------------------------------------------------
// kD: stage chunk Wh rows into smem (coalesced), local scan from smem,
//     serve chunk's queries. grid 512 = bh*8+ch, 256 threads.
// ---------------------------------------------------------------------------
#define D_STAGE  0        /* 128 x 64 */
#define D_LOCA   8192
#define D_LOCB   16384
#define D_WA     24576
#define D_WB     24704
#define D_TOT    24832
#define D_PRA    24896
#define D_PRB    24960
#define D_TPI    25024    /* 128 ints */
#define KD_FLOATS 25152
#define KD_SMEM (KD_FLOATS * 4)

__global__ __launch_bounds__(256) void kD_apply() {
    extern __shared__ float sm[];
    float* stage = sm + D_STAGE;
    float* locA = sm + D_LOCA;
    float* locB = sm + D_LOCB;
    float* wAs  = sm + D_WA;
    float* wBs  = sm + D_WB;
    float* Tot  = sm + D_TOT;
    float* prA  = sm + D_PRA;
    float* prB  = sm + D_PRB;
    int*   tpis = (int*)(sm + D_TPI);

    int tid = threadIdx.x;
    int bh = blockIdx.x >> 3, ch = blockIdx.x & 7;
    int b = bh >> 3, hh = bh & 7;
    int base = bh * NN;
    int cbase = base + ch * 128;

    if (tid < 128) {
        wAs[tid] = g_wA[cbase + tid];
        wBs[tid] = g_wB[cbase + tid];
        tpis[tid] = g_tpi[cbase + tid];
    } else if (tid < 192) {
        int d = tid - 128;
        Tot[d] = g_TotA[bh * 64 + d];
        prA[d] = g_prA[(bh * 8 + ch) * 64 + d];
        prB[d] = g_prB[(bh * 8 + ch) * 64 + d];
    }
    __syncthreads();

    // stage: 128 rows x 64 floats, coalesced float4 gather
#pragma unroll
    for (int p = 0; p < 8; p++) {
        int idx = p * 256 + tid;        // 0..2047
        int m = idx >> 4, f4 = idx & 15;
        *(float4*)&stage[m * 64 + f4 * 4] =
            *(const float4*)&g_Wh[(size_t)(b * NN + tpis[m]) * CC + hh * DD + f4 * 4];
    }
    __syncthreads();

    if (tid < 128) {
        int half = tid >> 6, d = tid & 63;
        const float* w = half ? wBs : wAs;
        float* loc = half ? locB : locA;
        float run = 0.f;
#pragma unroll 8
        for (int m = 0; m < 128; m++) {
            run = fmaf(w[m], stage[m * 64 + d], run);
            loc[m * 64 + d] = run;
        }
    }
    __syncthreads();

    {
        int qs = g_bofG[bh * 16 + ch + 1];
        int qe = g_bofG[bh * 16 + ch + 2];
        int qg = tid >> 6, d = tid & 63;
        for (int q = qs + qg; q < qe; q += 4) {
            int i = g_qord[base + q];
            int off = g_ci[base + i] - ch * 128 - 1;
            float es = g_es[base + i], es01 = g_es01[base + i];
            float val = es * (Tot[d] - prA[d] - locA[off * 64 + d])
                      + es01 * (prB[d] + locB[off * 64 + d]);
            g_hp[(size_t)(b * NN + i) * CC + hh * DD + d] = val;
        }
        if (ch == 0) {
            int q0 = g_bofG[bh * 16 + 0];
            int q1 = g_bofG[bh * 16 + 1];
            for (int q = q0 + qg; q < q1; q += 4) {
                int i = g_qord[base + q];
                float es = g_es[base + i];
                g_hp[(size_t)(b * NN + i) * CC + hh * DD + d] = es * Tot[d];
            }
        }
    }
}

// ---------------------------------------------------------------------------
// K5: out = h_prime @ out_W + out_b  [8192 x 512] @ [512 x 64]
// 32-row tiles, grid 256, float4 loads.
// ---------------------------------------------------------------------------
__global__ __launch_bounds__(256) void k5_out(const float* __restrict__ oW,
                                              const float* __restrict__ ob,
                                              float* __restrict__ out) {
    __shared__ __align__(16) float As[32][68];
    __shared__ __align__(16) float Bs[64][68];
    int tid = threadIdx.x;
    int r0 = blockIdx.x * 32;
    int tx = tid & 15, ty = tid >> 4;
    float acc[2][4] = {};
    for (int kt = 0; kt < CC; kt += 64) {
        __syncthreads();
#pragma unroll
        for (int p = 0; p < 2; p++) {
            int idx = p * 256 + tid;      // 0..511
            int r = idx >> 4, k4 = idx & 15;
            *(float4*)&As[r][k4*4] = *(const float4*)&g_hp[(size_t)(r0 + r) * CC + kt + k4*4];
        }
#pragma unroll
        for (int p = 0; p < 4; p++) {
            int idx = p * 256 + tid;      // 0..1023
            int r = idx >> 4, k4 = idx & 15;
            *(float4*)&Bs[r][k4*4] = *(const float4*)&oW[(size_t)(kt + r) * DD + k4*4];
        }
        __syncthreads();
#pragma unroll
        for (int k4 = 0; k4 < 16; k4++) {
            float4 a4[2], b4[4];
#pragma unroll
            for (int r = 0; r < 2; r++) a4[r] = *(const float4*)&As[ty*2+r][k4*4];
#pragma unroll
            for (int kk = 0; kk < 4; kk++) b4[kk] = *(const float4*)&Bs[k4*4+kk][tx*4];
#pragma unroll
            for (int kk = 0; kk < 4; kk++) {
                float ak[2] = { kk==0?a4[0].x:kk==1?a4[0].y:kk==2?a4[0].z:a4[0].w,
                                kk==0?a4[1].x:kk==1?a4[1].y:kk==2?a4[1].z:a4[1].w };
                float bk[4] = { b4[kk].x, b4[kk].y, b4[kk].z, b4[kk].w };
#pragma unroll
                for (int r = 0; r < 2; r++)
#pragma unroll
                    for (int c = 0; c < 4; c++)
                        acc[r][c] = fmaf(ak[r], bk[c], acc[r][c]);
            }
        }
    }
    float b0 = ob[tx*4+0], b1 = ob[tx*4+1], b2 = ob[tx*4+2], b3 = ob[tx*4+3];
#pragma unroll
    for (int r = 0; r < 2; r++) {
        float4 o = {acc[r][0] + b0, acc[r][1] + b1, acc[r][2] + b2, acc[r][3] + b3};
        *(float4*)&out[(size_t)(r0 + ty*2 + r) * DD + tx*4] = o;
    }
}

// ---------------------------------------------------------------------------
extern "C" void kernel_launch(void* const* d_in, const int* in_sizes, int n_in,
                              void* d_out, int out_size) {
    const float* h    = (const float*)d_in[0];
    const float* W    = (const float*)d_in[2];
    const float* a    = (const float*)d_in[3];
    const float* oW   = (const float*)d_in[4];
    const float* ob   = (const float*)d_in[5];
    float* out = (float*)d_out;

    cudaFuncSetAttribute(kS_all, cudaFuncAttributeMaxDynamicSharedMemorySize,
                         KS_SMEM);
    cudaFuncSetAttribute(kD_apply, cudaFuncAttributeMaxDynamicSharedMemorySize,
                         KD_SMEM);

    k1x<<<dim3(HH, (BB*NN)/64), 256>>>(h, W, a);
    kS_all<<<BB*HH, 1024, KS_SMEM>>>();
    kD_apply<<<BB*HH*8, 256, KD_SMEM>>>();
    k5_out<<<(BB*NN)/32, 256>>>(oW, ob, out);
}

// round 9
// speedup vs baseline: 1.8496x; 1.1248x over previous
#include <cuda_runtime.h>
#include <cuda_bf16.h>
#include <cstdint>
#include <cstddef>

#define BB 8
#define NN 1024
#define HH 8
#define DD 64
#define CC (HH*DD)   // 512

// Scratch
__device__ __nv_bfloat16 g_hpH[BB*NN*CC];
__device__ __nv_bfloat16 g_hpL[BB*NN*CC];
__device__ __nv_bfloat16 g_oWH[CC*DD];
__device__ __nv_bfloat16 g_oWL[CC*DD];
__device__ float g_s   [BB*HH*NN];
__device__ float g_t   [BB*HH*NN];
__device__ float g_es  [BB*HH*NN];
__device__ float g_es01[BB*HH*NN];
__device__ float g_et  [BB*HH*NN];
__device__ float g_et01[BB*HH*NN];
__device__ float g_Wh[BB*NN*CC];
// sort/scan pipeline scratch
__device__ int   g_tpi [BB*HH*NN];
__device__ float g_wA  [BB*HH*NN];
__device__ float g_wB  [BB*HH*NN];
__device__ int   g_ci  [BB*HH*NN];
__device__ int   g_qord[BB*HH*NN];
__device__ int   g_bofG[BB*HH*16];
__device__ float g_prA [BB*HH*8*64];
__device__ float g_prB [BB*HH*8*64];
__device__ float g_TotA[BB*HH*64];

__device__ __forceinline__ uint32_t smem_u32(const void* p) {
    uint32_t a;
    asm("{ .reg .u64 t; cvta.to.shared.u64 t, %1; cvt.u32.u64 %0, t; }" : "=r"(a) : "l"(p));
    return a;
}
#define LDSM4(r0, r1, r2, r3, addr) \
    asm volatile("ldmatrix.sync.aligned.m8n8.x4.shared.b16 {%0,%1,%2,%3}, [%4];" \
                 : "=r"(r0), "=r"(r1), "=r"(r2), "=r"(r3) : "r"(addr))
#define LDSM_T4(r0, r1, r2, r3, addr) \
    asm volatile("ldmatrix.sync.aligned.m8n8.x4.trans.shared.b16 {%0,%1,%2,%3}, [%4];" \
                 : "=r"(r0), "=r"(r1), "=r"(r2), "=r"(r3) : "r"(addr))
#define MMA16816(d0,d1,d2,d3, a0,a1,a2,a3, b0,b1) \
    asm volatile("mma.sync.aligned.m16n8k16.row.col.f32.bf16.bf16.f32 " \
                 "{%0,%1,%2,%3}, {%4,%5,%6,%7}, {%8,%9}, {%0,%1,%2,%3};" \
                 : "+f"(d0), "+f"(d1), "+f"(d2), "+f"(d3) \
                 : "r"(a0), "r"(a1), "r"(a2), "r"(a3), "r"(b0), "r"(b1))

// ---------------------------------------------------------------------------
// kW: split out_W into bf16 hi/lo. 32768 elems; 128 blocks x 256.
// ---------------------------------------------------------------------------
__global__ __launch_bounds__(256) void kW_conv(const float* __restrict__ oW) {
    int i = blockIdx.x * 256 + threadIdx.x;
    float v = oW[i];
    __nv_bfloat16 hi = __float2bfloat16_rn(v);
    g_oWH[i] = hi;
    g_oWL[i] = __float2bfloat16_rn(v - __bfloat162float(hi));
}

// ---------------------------------------------------------------------------
// k1x: Wh = h @ W (64-row x one-head tile per block) fused with s/t/exp.
// ---------------------------------------------------------------------------
__global__ __launch_bounds__(256) void k1x(const float* __restrict__ h,
                                           const float* __restrict__ W,
                                           const float* __restrict__ a) {
    __shared__ __align__(16) float As[64][68];   // [row][k]
    __shared__ __align__(16) float Bs[64][68];   // [k][col]
    __shared__ float as[128];
    __shared__ float sred[64][17], tred[64][17];
    int tid = threadIdx.x;
    int hh = blockIdx.x;
    int r0 = blockIdx.y * 64;
    int c0 = hh * 64;
    if (tid < 128) as[tid] = a[tid];
#pragma unroll
    for (int p = 0; p < 4; p++) {
        int idx = p * 256 + tid;
        int r = idx >> 4, k4 = idx & 15;
        *(float4*)&As[r][k4*4] = *(const float4*)&h[(size_t)(r0 + r) * 64 + k4*4];
        *(float4*)&Bs[r][k4*4] = *(const float4*)&W[(size_t)r * CC + c0 + k4*4];
    }
    __syncthreads();
    int tx = tid & 15, ty = tid >> 4;
    float acc[4][4] = {};
#pragma unroll
    for (int k4 = 0; k4 < 16; k4++) {
        float4 a4[4], b4[4];
#pragma unroll
        for (int r = 0; r < 4; r++) a4[r] = *(const float4*)&As[ty*4+r][k4*4];
#pragma unroll
        for (int kk = 0; kk < 4; kk++) b4[kk] = *(const float4*)&Bs[k4*4+kk][tx*4];
#pragma unroll
        for (int kk = 0; kk < 4; kk++) {
            float ak[4] = { kk==0?a4[0].x:kk==1?a4[0].y:kk==2?a4[0].z:a4[0].w,
                            kk==0?a4[1].x:kk==1?a4[1].y:kk==2?a4[1].z:a4[1].w,
                            kk==0?a4[2].x:kk==1?a4[2].y:kk==2?a4[2].z:a4[2].w,
                            kk==0?a4[3].x:kk==1?a4[3].y:kk==2?a4[3].z:a4[3].w };
            float bk[4] = { b4[kk].x, b4[kk].y, b4[kk].z, b4[kk].w };
#pragma unroll
            for (int r = 0; r < 4; r++)
#pragma unroll
                for (int c = 0; c < 4; c++)
                    acc[r][c] = fmaf(ak[r], bk[c], acc[r][c]);
        }
    }
#pragma unroll
    for (int r = 0; r < 4; r++) {
        float4 o = {acc[r][0], acc[r][1], acc[r][2], acc[r][3]};
        *(float4*)&g_Wh[(size_t)(r0 + ty*4 + r) * CC + c0 + tx*4] = o;
        float ps = 0.f, pt = 0.f;
#pragma unroll
        for (int c = 0; c < 4; c++) {
            ps = fmaf(acc[r][c], as[tx*4 + c], ps);
            pt = fmaf(acc[r][c], as[64 + tx*4 + c], pt);
        }
        sred[ty*4 + r][tx] = ps;
        tred[ty*4 + r][tx] = pt;
    }
    __syncthreads();
    if (tid < 64) {
        float s = 0.f, t = 0.f;
#pragma unroll
        for (int x = 0; x < 16; x++) { s += sred[tid][x]; t += tred[tid][x]; }
        int gr = r0 + tid;
        int b = gr >> 10, n = gr & (NN - 1);
        int o = (b * HH + hh) * NN + n;
        g_s[o] = s;                 g_t[o] = t;
        g_es[o]   = __expf(s);      g_es01[o] = __expf(0.01f * s);
        g_et[o]   = __expf(t);      g_et01[o] = __expf(0.01f * t);
    }
}

// ---------------------------------------------------------------------------
__device__ __forceinline__ int ub1024(const float* __restrict__ arr, float key) {
    int lo = 0, hi = 1024;
    while (lo < hi) {
        int mid = (lo + hi) >> 1;
        if (arr[mid] <= key) lo = mid + 1; else hi = mid;
    }
    return lo;
}

// ---------------------------------------------------------------------------
// kS: one block per (b,h), 1024 threads. Sorts, scans, Z, buckets, coarse sums.
// ---------------------------------------------------------------------------
#define S_SV    0
#define S_TV    1024
#define S_SIDX  2048
#define S_TPI   3072
#define S_SCANA 4096
#define S_SCANB 6144
#define S_WAS   8192
#define S_WBS   9216
#define S_PARTA 10240
#define S_PARTB 11264
#define S_BOFF  12288
#define S_CNT   12304
#define KS_FLOATS 12320
#define KS_SMEM (KS_FLOATS * 4)

__global__ __launch_bounds__(1024) void kS_all() {
    extern __shared__ float sm[];
    float* sv    = sm + S_SV;
    float* tv    = sm + S_TV;
    int*   sidx  = (int*)(sm + S_SIDX);
    int*   tpi   = (int*)(sm + S_TPI);
    float* scanA = sm + S_SCANA;
    float* scanB = sm + S_SCANB;
    float* wAs   = sm + S_WAS;
    float* wBs   = sm + S_WBS;
    float* partA = sm + S_PARTA;
    float* partB = sm + S_PARTB;
    int*   boff  = (int*)(sm + S_BOFF);
    int*   cnt   = (int*)(sm + S_CNT);

    int tid = threadIdx.x;
    int bh = blockIdx.x;
    int b = bh >> 3, hh = bh & 7;
    int base = bh * NN;

    float s0 = g_s[base + tid];
    sv[tid] = s0;  sidx[tid] = tid;
    tv[tid] = g_t[base + tid];  tpi[tid] = tid;
    if (tid < 16) { boff[tid] = 0; cnt[tid] = 0; }
    __syncthreads();

    for (int k = 2; k <= 1024; k <<= 1) {
        for (int j = k >> 1; j > 0; j >>= 1) {
            int ixj = tid ^ j;
            if (ixj > tid) {
                bool up = ((tid & k) == 0);
                float av = sv[tid], bv = sv[ixj];
                if ((av > bv) == up) {
                    sv[tid] = bv; sv[ixj] = av;
                    int tmp = sidx[tid]; sidx[tid] = sidx[ixj]; sidx[ixj] = tmp;
                }
                float at = tv[tid], bt = tv[ixj];
                if ((at > bt) == up) {
                    tv[tid] = bt; tv[ixj] = at;
                    int tmp = tpi[tid]; tpi[tid] = tpi[ixj]; tpi[ixj] = tmp;
                }
            }
            __syncthreads();
        }
    }

    {
        int io = sidx[tid];
        scanA[tid] = g_es[base + io];
        scanB[tid] = g_es01[base + io];
    }
    __syncthreads();
    int src = 0;
    for (int d = 1; d < 1024; d <<= 1) {
        float aA = scanA[src*1024 + tid], aB = scanB[src*1024 + tid];
        if (tid >= d) {
            aA += scanA[src*1024 + tid - d];
            aB += scanB[src*1024 + tid - d];
        }
        scanA[(1 - src)*1024 + tid] = aA;
        scanB[(1 - src)*1024 + tid] = aB;
        __syncthreads();
        src ^= 1;
    }
    const float* inclA = scanA + src * 1024;
    const float* inclB = scanB + src * 1024;
    float ES_tot = inclA[1023];

    {
        int cpr = ub1024(sv, -tv[tid]);
        int jo = tpi[tid];
        float et = g_et[base + jo], et01 = g_et01[base + jo];
        float pa = cpr ? inclA[cpr - 1] : 0.f;
        float pb = cpr ? inclB[cpr - 1] : 0.f;
        float rz = 1.f / (et * (ES_tot - pa) + et01 * pb);
        float wa = et * rz, wb = et01 * rz;
        wAs[tid] = wa;  wBs[tid] = wb;
        g_wA[base + tid] = wa;
        g_wB[base + tid] = wb;
        g_tpi[base + tid] = jo;
    }

    {
        int c = ub1024(tv, -s0);
        g_ci[base + tid] = c;
        int bu = (c == 0) ? 0 : (1 + ((c - 1) >> 7));
        atomicAdd(&boff[bu + 1], 1);
    }
    __syncthreads();

    {
        int ch = tid >> 7;
        int mh = (tid >> 6) & 1;
        int d = tid & 63;
        int m0 = ch * 128 + mh * 64;
        float pa = 0.f, pb = 0.f;
#pragma unroll 4
        for (int q = 0; q < 64; q++) {
            int m = m0 + q;
            float v = g_Wh[(size_t)(b * NN + tpi[m]) * CC + hh * DD + d];
            pa = fmaf(wAs[m], v, pa);
            pb = fmaf(wBs[m], v, pb);
        }
        partA[(ch * 2 + mh) * 64 + d] = pa;
        partB[(ch * 2 + mh) * 64 + d] = pb;
    }
    __syncthreads();

    if (tid == 0)
        for (int q = 1; q <= 9; q++) boff[q] += boff[q - 1];
    __syncthreads();

    {
        int c = g_ci[base + tid];
        int bu = (c == 0) ? 0 : (1 + ((c - 1) >> 7));
        int pos = boff[bu] + atomicAdd(&cnt[bu], 1);
        g_qord[base + pos] = tid;
    }
    if (tid < 16) g_bofG[bh * 16 + tid] = boff[tid];

    if (tid < 64) {
        int d = tid;
        float pa = 0.f, pb = 0.f;
#pragma unroll
        for (int ch = 0; ch < 8; ch++) {
            int o = (bh * 8 + ch) * 64 + d;
            g_prA[o] = pa;  g_prB[o] = pb;
            pa += partA[(ch * 2) * 64 + d] + partA[(ch * 2 + 1) * 64 + d];
            pb += partB[(ch * 2) * 64 + d] + partB[(ch * 2 + 1) * 64 + d];
        }
        g_TotA[bh * 64 + d] = pa;
    }
}

// ---------------------------------------------------------------------------
// kD: stage chunk Wh rows into smem, local scan, serve queries; write h'
//     as bf16 hi/lo.  grid 512 = bh*8+ch, 256 threads, dynamic smem.
// ---------------------------------------------------------------------------
#define D_STAGE  0
#define D_LOCA   8192
#define D_LOCB   16384
#define D_WA     24576
#define D_WB     24704
#define D_TOT    24832
#define D_PRA    24896
#define D_PRB    24960
#define D_TPI    25024
#define KD_FLOATS 25152
#define KD_SMEM (KD_FLOATS * 4)

__device__ __forceinline__ void store_hilo(size_t o, float val) {
    __nv_bfloat16 hi = __float2bfloat16_rn(val);
    g_hpH[o] = hi;
    g_hpL[o] = __float2bfloat16_rn(val - __bfloat162float(hi));
}

__global__ __launch_bounds__(256) void kD_apply() {
    extern __shared__ float sm[];
    float* stage = sm + D_STAGE;
    float* locA = sm + D_LOCA;
    float* locB = sm + D_LOCB;
    float* wAs  = sm + D_WA;
    float* wBs  = sm + D_WB;
    float* Tot  = sm + D_TOT;
    float* prA  = sm + D_PRA;
    float* prB  = sm + D_PRB;
    int*   tpis = (int*)(sm + D_TPI);

    int tid = threadIdx.x;
    int bh = blockIdx.x >> 3, ch = blockIdx.x & 7;
    int b = bh >> 3, hh = bh & 7;
    int base = bh * NN;
    int cbase = base + ch * 128;

    if (tid < 128) {
        wAs[tid] = g_wA[cbase + tid];
        wBs[tid] = g_wB[cbase + tid];
        tpis[tid] = g_tpi[cbase + tid];
    } else if (tid < 192) {
        int d = tid - 128;
        Tot[d] = g_TotA[bh * 64 + d];
        prA[d] = g_prA[(bh * 8 + ch) * 64 + d];
        prB[d] = g_prB[(bh * 8 + ch) * 64 + d];
    }
    __syncthreads();

#pragma unroll
    for (int p = 0; p < 8; p++) {
        int idx = p * 256 + tid;
        int m = idx >> 4, f4 = idx & 15;
        *(float4*)&stage[m * 64 + f4 * 4] =
            *(const float4*)&g_Wh[(size_t)(b * NN + tpis[m]) * CC + hh * DD + f4 * 4];
    }
    __syncthreads();

    if (tid < 128) {
        int half = tid >> 6, d = tid & 63;
        const float* w = half ? wBs : wAs;
        float* loc = half ? locB : locA;
        float run = 0.f;
#pragma unroll 8
        for (int m = 0; m < 128; m++) {
            run = fmaf(w[m], stage[m * 64 + d], run);
            loc[m * 64 + d] = run;
        }
    }
    __syncthreads();

    {
        int qs = g_bofG[bh * 16 + ch + 1];
        int qe = g_bofG[bh * 16 + ch + 2];
        int qg = tid >> 6, d = tid & 63;
        for (int q = qs + qg; q < qe; q += 4) {
            int i = g_qord[base + q];
            int off = g_ci[base + i] - ch * 128 - 1;
            float es = g_es[base + i], es01 = g_es01[base + i];
            float val = es * (Tot[d] - prA[d] - locA[off * 64 + d])
                      + es01 * (prB[d] + locB[off * 64 + d]);
            store_hilo((size_t)(b * NN + i) * CC + hh * DD + d, val);
        }
        if (ch == 0) {
            int q0 = g_bofG[bh * 16 + 0];
            int q1 = g_bofG[bh * 16 + 1];
            for (int q = q0 + qg; q < q1; q += 4) {
                int i = g_qord[base + q];
                float es = g_es[base + i];
                store_hilo((size_t)(b * NN + i) * CC + hh * DD + d, es * Tot[d]);
            }
        }
    }
}

// ---------------------------------------------------------------------------
// k5m: out = h' @ out_W + b via mma.sync bf16 hi/lo (3 MMAs, fp32 acc).
// grid 256 (32 rows each), 256 threads = 8 warps: warp w -> mi=w&1 (m16),
// nc=w>>1 (n16 = two n8 tiles). K chunks of 64.
// ---------------------------------------------------------------------------
__global__ __launch_bounds__(256) void k5m(const float* __restrict__ ob,
                                           float* __restrict__ out) {
    __shared__ __align__(16) __nv_bfloat16 Ah[32][72];
    __shared__ __align__(16) __nv_bfloat16 Al[32][72];
    __shared__ __align__(16) __nv_bfloat16 Bh[64][72];
    __shared__ __align__(16) __nv_bfloat16 Bl[64][72];
    int tid = threadIdx.x, lane = tid & 31, w = tid >> 5;
    int mi = w & 1, nc = w >> 1;
    int r0 = blockIdx.x * 32;

    // ldmatrix lane addresses
    uint32_t aoff = (uint32_t)(((((lane >> 3) & 1) * 8 + (lane & 7)) + mi * 16) * 72
                               + (lane >> 4) * 8) * 2;
    uint32_t boff = (uint32_t)((lane & 15) * 72 + (lane >> 4) * 8) * 2
                    + (uint32_t)nc * 32;
    uint32_t aAh = smem_u32(Ah) + aoff;
    uint32_t aAl = smem_u32(Al) + aoff;
    uint32_t aBh = smem_u32(Bh) + boff;
    uint32_t aBl = smem_u32(Bl) + boff;

    float acc[2][4] = {};

    for (int kt = 0; kt < CC; kt += 64) {
        __syncthreads();
        {   // A fill: 32 rows x 8 groups of 8 bf16, hi+lo
            int row = tid >> 3, g = tid & 7;
            *(uint4*)&Ah[row][g*8] =
                *(const uint4*)&g_hpH[(size_t)(r0 + row) * CC + kt + g*8];
            *(uint4*)&Al[row][g*8] =
                *(const uint4*)&g_hpL[(size_t)(r0 + row) * CC + kt + g*8];
        }
#pragma unroll
        for (int p = 0; p < 2; p++) {   // B fill: 64 rows x 8 groups
            int idx = p * 256 + tid;
            int row = idx >> 3, g = idx & 7;
            *(uint4*)&Bh[row][g*8] = *(const uint4*)&g_oWH[(size_t)(kt + row) * 64 + g*8];
            *(uint4*)&Bl[row][g*8] = *(const uint4*)&g_oWL[(size_t)(kt + row) * 64 + g*8];
        }
        __syncthreads();

#pragma unroll
        for (int kk = 0; kk < 4; kk++) {
            uint32_t ka = (uint32_t)(kk * 32);       // 16 bf16 along k
            uint32_t kb = (uint32_t)(kk * 16 * 144); // 16 k-rows
            uint32_t ah0, ah1, ah2, ah3, al0, al1, al2, al3;
            uint32_t bh0, bh1, bh2, bh3, bl0, bl1, bl2, bl3;
            LDSM4(ah0, ah1, ah2, ah3, aAh + ka);
            LDSM4(al0, al1, al2, al3, aAl + ka);
            LDSM_T4(bh0, bh1, bh2, bh3, aBh + kb);
            LDSM_T4(bl0, bl1, bl2, bl3, aBl + kb);
            MMA16816(acc[0][0], acc[0][1], acc[0][2], acc[0][3],
                     ah0, ah1, ah2, ah3, bh0, bh1);
            MMA16816(acc[1][0], acc[1][1], acc[1][2], acc[1][3],
                     ah0, ah1, ah2, ah3, bh2, bh3);
            MMA16816(acc[0][0], acc[0][1], acc[0][2], acc[0][3],
                     ah0, ah1, ah2, ah3, bl0, bl1);
            MMA16816(acc[1][0], acc[1][1], acc[1][2], acc[1][3],
                     ah0, ah1, ah2, ah3, bl2, bl3);
            MMA16816(acc[0][0], acc[0][1], acc[0][2], acc[0][3],
                     al0, al1, al2, al3, bh0, bh1);
            MMA16816(acc[1][0], acc[1][1], acc[1][2], acc[1][3],
                     al0, al1, al2, al3, bh2, bh3);
        }
    }

    int gr = lane >> 2, c2 = (lane & 3) * 2;
    int row0 = r0 + mi * 16 + gr;
#pragma unroll
    for (int t = 0; t < 2; t++) {
        int col = nc * 16 + t * 8 + c2;
        float b0 = ob[col], b1 = ob[col + 1];
        float2 o0 = {acc[t][0] + b0, acc[t][1] + b1};
        float2 o1 = {acc[t][2] + b0, acc[t][3] + b1};
        *(float2*)&out[(size_t)row0 * DD + col] = o0;
        *(float2*)&out[(size_t)(row0 + 8) * DD + col] = o1;
    }
}

// ---------------------------------------------------------------------------
extern "C" void kernel_launch(void* const* d_in, const int* in_sizes, int n_in,
                              void* d_out, int out_size) {
    const float* h    = (const float*)d_in[0];
    const float* W    = (const float*)d_in[2];
    const float* a    = (const float*)d_in[3];
    const float* oW   = (const float*)d_in[4];
    const float* ob   = (const float*)d_in[5];
    float* out = (float*)d_out;

    cudaFuncSetAttribute(kS_all, cudaFuncAttributeMaxDynamicSharedMemorySize,
                         KS_SMEM);
    cudaFuncSetAttribute(kD_apply, cudaFuncAttributeMaxDynamicSharedMemorySize,
                         KD_SMEM);

    kW_conv<<<(CC*DD)/256, 256>>>(oW);
    k1x<<<dim3(HH, (BB*NN)/64), 256>>>(h, W, a);
    kS_all<<<BB*HH, 1024, KS_SMEM>>>();
    kD_apply<<<BB*HH*8, 256, KD_SMEM>>>();
    k5m<<<(BB*NN)/32, 256>>>(ob, out);
}

// round 10
// speedup vs baseline: 2.1455x; 1.1599x over previous
#include <cuda_runtime.h>
#include <cuda_bf16.h>
#include <cstdint>
#include <cstddef>

#define BB 8
#define NN 1024
#define HH 8
#define DD 64
#define CC (HH*DD)   // 512

// Scratch
__device__ __nv_bfloat16 g_hpH[BB*NN*CC];
__device__ __nv_bfloat16 g_hpL[BB*NN*CC];
__device__ __nv_bfloat16 g_oWH[CC*DD];
__device__ __nv_bfloat16 g_oWL[CC*DD];
__device__ float g_s   [BB*HH*NN];
__device__ float g_t   [BB*HH*NN];
__device__ float g_es  [BB*HH*NN];
__device__ float g_es01[BB*HH*NN];
__device__ float g_et  [BB*HH*NN];
__device__ float g_et01[BB*HH*NN];
__device__ float g_Wh[BB*NN*CC];
// sort/scan pipeline scratch
__device__ int   g_tpi [BB*HH*NN];
__device__ float g_wA  [BB*HH*NN];
__device__ float g_wB  [BB*HH*NN];
__device__ int   g_ci  [BB*HH*NN];
__device__ int   g_qord[BB*HH*NN];
__device__ int   g_bofG[BB*HH*16];
__device__ float g_prA [BB*HH*8*64];
__device__ float g_prB [BB*HH*8*64];
__device__ float g_TotA[BB*HH*64];

__device__ __forceinline__ uint32_t smem_u32(const void* p) {
    uint32_t a;
    asm("{ .reg .u64 t; cvta.to.shared.u64 t, %1; cvt.u32.u64 %0, t; }" : "=r"(a) : "l"(p));
    return a;
}
#define LDSM4(r0, r1, r2, r3, addr) \
    asm volatile("ldmatrix.sync.aligned.m8n8.x4.shared.b16 {%0,%1,%2,%3}, [%4];" \
                 : "=r"(r0), "=r"(r1), "=r"(r2), "=r"(r3) : "r"(addr))
#define LDSM_T4(r0, r1, r2, r3, addr) \
    asm volatile("ldmatrix.sync.aligned.m8n8.x4.trans.shared.b16 {%0,%1,%2,%3}, [%4];" \
                 : "=r"(r0), "=r"(r1), "=r"(r2), "=r"(r3) : "r"(addr))
#define MMA16816(d0,d1,d2,d3, a0,a1,a2,a3, b0,b1) \
    asm volatile("mma.sync.aligned.m16n8k16.row.col.f32.bf16.bf16.f32 " \
                 "{%0,%1,%2,%3}, {%4,%5,%6,%7}, {%8,%9}, {%0,%1,%2,%3};" \
                 : "+f"(d0), "+f"(d1), "+f"(d2), "+f"(d3) \
                 : "r"(a0), "r"(a1), "r"(a2), "r"(a3), "r"(b0), "r"(b1))

// ---------------------------------------------------------------------------
// kW: split out_W into bf16 hi/lo.
// ---------------------------------------------------------------------------
__global__ __launch_bounds__(256) void kW_conv(const float* __restrict__ oW) {
    int i = blockIdx.x * 256 + threadIdx.x;
    float v = oW[i];
    __nv_bfloat16 hi = __float2bfloat16_rn(v);
    g_oWH[i] = hi;
    g_oWL[i] = __float2bfloat16_rn(v - __bfloat162float(hi));
}

// ---------------------------------------------------------------------------
// k1x: Wh = h @ W (64-row x one-head tile per block) fused with s/t/exp.
// ---------------------------------------------------------------------------
__global__ __launch_bounds__(256) void k1x(const float* __restrict__ h,
                                           const float* __restrict__ W,
                                           const float* __restrict__ a) {
    __shared__ __align__(16) float As[64][68];   // [row][k]
    __shared__ __align__(16) float Bs[64][68];   // [k][col]
    __shared__ float as[128];
    __shared__ float sred[64][17], tred[64][17];
    int tid = threadIdx.x;
    int hh = blockIdx.x;
    int r0 = blockIdx.y * 64;
    int c0 = hh * 64;
    if (tid < 128) as[tid] = a[tid];
#pragma unroll
    for (int p = 0; p < 4; p++) {
        int idx = p * 256 + tid;
        int r = idx >> 4, k4 = idx & 15;
        *(float4*)&As[r][k4*4] = *(const float4*)&h[(size_t)(r0 + r) * 64 + k4*4];
        *(float4*)&Bs[r][k4*4] = *(const float4*)&W[(size_t)r * CC + c0 + k4*4];
    }
    __syncthreads();
    int tx = tid & 15, ty = tid >> 4;
    float acc[4][4] = {};
#pragma unroll
    for (int k4 = 0; k4 < 16; k4++) {
        float4 a4[4], b4[4];
#pragma unroll
        for (int r = 0; r < 4; r++) a4[r] = *(const float4*)&As[ty*4+r][k4*4];
#pragma unroll
        for (int kk = 0; kk < 4; kk++) b4[kk] = *(const float4*)&Bs[k4*4+kk][tx*4];
#pragma unroll
        for (int kk = 0; kk < 4; kk++) {
            float ak[4] = { kk==0?a4[0].x:kk==1?a4[0].y:kk==2?a4[0].z:a4[0].w,
                            kk==0?a4[1].x:kk==1?a4[1].y:kk==2?a4[1].z:a4[1].w,
                            kk==0?a4[2].x:kk==1?a4[2].y:kk==2?a4[2].z:a4[2].w,
                            kk==0?a4[3].x:kk==1?a4[3].y:kk==2?a4[3].z:a4[3].w };
            float bk[4] = { b4[kk].x, b4[kk].y, b4[kk].z, b4[kk].w };
#pragma unroll
            for (int r = 0; r < 4; r++)
#pragma unroll
                for (int c = 0; c < 4; c++)
                    acc[r][c] = fmaf(ak[r], bk[c], acc[r][c]);
        }
    }
#pragma unroll
    for (int r = 0; r < 4; r++) {
        float4 o = {acc[r][0], acc[r][1], acc[r][2], acc[r][3]};
        *(float4*)&g_Wh[(size_t)(r0 + ty*4 + r) * CC + c0 + tx*4] = o;
        float ps = 0.f, pt = 0.f;
#pragma unroll
        for (int c = 0; c < 4; c++) {
            ps = fmaf(acc[r][c], as[tx*4 + c], ps);
            pt = fmaf(acc[r][c], as[64 + tx*4 + c], pt);
        }
        sred[ty*4 + r][tx] = ps;
        tred[ty*4 + r][tx] = pt;
    }
    __syncthreads();
    if (tid < 64) {
        float s = 0.f, t = 0.f;
#pragma unroll
        for (int x = 0; x < 16; x++) { s += sred[tid][x]; t += tred[tid][x]; }
        int gr = r0 + tid;
        int b = gr >> 10, n = gr & (NN - 1);
        int o = (b * HH + hh) * NN + n;
        g_s[o] = s;                 g_t[o] = t;
        g_es[o]   = __expf(s);      g_es01[o] = __expf(0.01f * s);
        g_et[o]   = __expf(t);      g_et01[o] = __expf(0.01f * t);
    }
}

// ---------------------------------------------------------------------------
__device__ __forceinline__ int ub1024(const float* __restrict__ arr, float key) {
    int lo = 0, hi = 1024;
    while (lo < hi) {
        int mid = (lo + hi) >> 1;
        if (arr[mid] <= key) lo = mid + 1; else hi = mid;
    }
    return lo;
}

// ---------------------------------------------------------------------------
// kS: one block per (b,h), 1024 threads. Sorts, scans, Z, buckets, coarse sums.
// ---------------------------------------------------------------------------
#define S_SV    0
#define S_TV    1024
#define S_SIDX  2048
#define S_TPI   3072
#define S_SCANA 4096
#define S_SCANB 6144
#define S_WAS   8192
#define S_WBS   9216
#define S_PARTA 10240
#define S_PARTB 11264
#define S_BOFF  12288
#define S_CNT   12304
#define KS_FLOATS 12320
#define KS_SMEM (KS_FLOATS * 4)

__global__ __launch_bounds__(1024) void kS_all() {
    extern __shared__ float sm[];
    float* sv    = sm + S_SV;
    float* tv    = sm + S_TV;
    int*   sidx  = (int*)(sm + S_SIDX);
    int*   tpi   = (int*)(sm + S_TPI);
    float* scanA = sm + S_SCANA;
    float* scanB = sm + S_SCANB;
    float* wAs   = sm + S_WAS;
    float* wBs   = sm + S_WBS;
    float* partA = sm + S_PARTA;
    float* partB = sm + S_PARTB;
    int*   boff  = (int*)(sm + S_BOFF);
    int*   cnt   = (int*)(sm + S_CNT);

    int tid = threadIdx.x;
    int bh = blockIdx.x;
    int b = bh >> 3, hh = bh & 7;
    int base = bh * NN;

    float s0 = g_s[base + tid];
    sv[tid] = s0;  sidx[tid] = tid;
    tv[tid] = g_t[base + tid];  tpi[tid] = tid;
    if (tid < 16) { boff[tid] = 0; cnt[tid] = 0; }
    __syncthreads();

    for (int k = 2; k <= 1024; k <<= 1) {
        for (int j = k >> 1; j > 0; j >>= 1) {
            int ixj = tid ^ j;
            if (ixj > tid) {
                bool up = ((tid & k) == 0);
                float av = sv[tid], bv = sv[ixj];
                if ((av > bv) == up) {
                    sv[tid] = bv; sv[ixj] = av;
                    int tmp = sidx[tid]; sidx[tid] = sidx[ixj]; sidx[ixj] = tmp;
                }
                float at = tv[tid], bt = tv[ixj];
                if ((at > bt) == up) {
                    tv[tid] = bt; tv[ixj] = at;
                    int tmp = tpi[tid]; tpi[tid] = tpi[ixj]; tpi[ixj] = tmp;
                }
            }
            __syncthreads();
        }
    }

    {
        int io = sidx[tid];
        scanA[tid] = g_es[base + io];
        scanB[tid] = g_es01[base + io];
    }
    __syncthreads();
    int src = 0;
    for (int d = 1; d < 1024; d <<= 1) {
        float aA = scanA[src*1024 + tid], aB = scanB[src*1024 + tid];
        if (tid >= d) {
            aA += scanA[src*1024 + tid - d];
            aB += scanB[src*1024 + tid - d];
        }
        scanA[(1 - src)*1024 + tid] = aA;
        scanB[(1 - src)*1024 + tid] = aB;
        __syncthreads();
        src ^= 1;
    }
    const float* inclA = scanA + src * 1024;
    const float* inclB = scanB + src * 1024;
    float ES_tot = inclA[1023];

    {
        int cpr = ub1024(sv, -tv[tid]);
        int jo = tpi[tid];
        float et = g_et[base + jo], et01 = g_et01[base + jo];
        float pa = cpr ? inclA[cpr - 1] : 0.f;
        float pb = cpr ? inclB[cpr - 1] : 0.f;
        float rz = 1.f / (et * (ES_tot - pa) + et01 * pb);
        float wa = et * rz, wb = et01 * rz;
        wAs[tid] = wa;  wBs[tid] = wb;
        g_wA[base + tid] = wa;
        g_wB[base + tid] = wb;
        g_tpi[base + tid] = jo;
    }

    {
        int c = ub1024(tv, -s0);
        g_ci[base + tid] = c;
        int bu = (c == 0) ? 0 : (1 + ((c - 1) >> 7));
        atomicAdd(&boff[bu + 1], 1);
    }
    __syncthreads();

    {
        int ch = tid >> 7;
        int mh = (tid >> 6) & 1;
        int d = tid & 63;
        int m0 = ch * 128 + mh * 64;
        float pa = 0.f, pb = 0.f;
#pragma unroll 4
        for (int q = 0; q < 64; q++) {
            int m = m0 + q;
            float v = g_Wh[(size_t)(b * NN + tpi[m]) * CC + hh * DD + d];
            pa = fmaf(wAs[m], v, pa);
            pb = fmaf(wBs[m], v, pb);
        }
        partA[(ch * 2 + mh) * 64 + d] = pa;
        partB[(ch * 2 + mh) * 64 + d] = pb;
    }
    __syncthreads();

    if (tid == 0)
        for (int q = 1; q <= 9; q++) boff[q] += boff[q - 1];
    __syncthreads();

    {
        int c = g_ci[base + tid];
        int bu = (c == 0) ? 0 : (1 + ((c - 1) >> 7));
        int pos = boff[bu] + atomicAdd(&cnt[bu], 1);
        g_qord[base + pos] = tid;
    }
    if (tid < 16) g_bofG[bh * 16 + tid] = boff[tid];

    if (tid < 64) {
        int d = tid;
        float pa = 0.f, pb = 0.f;
#pragma unroll
        for (int ch = 0; ch < 8; ch++) {
            int o = (bh * 8 + ch) * 64 + d;
            g_prA[o] = pa;  g_prB[o] = pb;
            pa += partA[(ch * 2) * 64 + d] + partA[(ch * 2 + 1) * 64 + d];
            pb += partB[(ch * 2) * 64 + d] + partB[(ch * 2 + 1) * 64 + d];
        }
        g_TotA[bh * 64 + d] = pa;
    }
}

// ---------------------------------------------------------------------------
// kD: stage chunk Wh rows into smem, local scan (threads 0-127) while
//     threads 128-255 gather this chunk's query metadata into smem in
//     parallel; then serve queries entirely from smem (no dependent global
//     load chains). Writes h' as bf16 hi/lo.
// grid 512 = bh*8+ch, 256 threads, dynamic smem (~110 KB, 2 CTA/SM).
// ---------------------------------------------------------------------------
#define D_STAGE  0        /* 128 x 64 */
#define D_LOCA   8192
#define D_LOCB   16384
#define D_WA     24576
#define D_WB     24704
#define D_TOT    24832
#define D_PRA    24896
#define D_PRB    24960
#define D_TPI    25024    /* 128 ints */
#define D_QPK    25152    /* 1024 ints: i | (off+1)<<16 */
#define D_QES    26176    /* 1024 floats */
#define D_QES01  27200    /* 1024 floats */
#define KD_FLOATS 28224
#define KD_SMEM (KD_FLOATS * 4)

__device__ __forceinline__ void store_hilo(size_t o, float val) {
    __nv_bfloat16 hi = __float2bfloat16_rn(val);
    g_hpH[o] = hi;
    g_hpL[o] = __float2bfloat16_rn(val - __bfloat162float(hi));
}

__global__ __launch_bounds__(256) void kD_apply() {
    extern __shared__ float sm[];
    float* stage = sm + D_STAGE;
    float* locA = sm + D_LOCA;
    float* locB = sm + D_LOCB;
    float* wAs  = sm + D_WA;
    float* wBs  = sm + D_WB;
    float* Tot  = sm + D_TOT;
    float* prA  = sm + D_PRA;
    float* prB  = sm + D_PRB;
    int*   tpis = (int*)(sm + D_TPI);
    int*   qpk  = (int*)(sm + D_QPK);
    float* qes  = sm + D_QES;
    float* qes01= sm + D_QES01;

    int tid = threadIdx.x;
    int bh = blockIdx.x >> 3, ch = blockIdx.x & 7;
    int b = bh >> 3, hh = bh & 7;
    int base = bh * NN;
    int cbase = base + ch * 128;

    // query range: ch 0 also serves bucket 0 (c==0); ranges are contiguous
    int qs = (ch == 0) ? g_bofG[bh * 16 + 0] : g_bofG[bh * 16 + ch + 1];
    int qe = g_bofG[bh * 16 + ch + 2];
    int nq = qe - qs;

    if (tid < 128) {
        wAs[tid] = g_wA[cbase + tid];
        wBs[tid] = g_wB[cbase + tid];
        tpis[tid] = g_tpi[cbase + tid];
    } else if (tid < 192) {
        int d = tid - 128;
        Tot[d] = g_TotA[bh * 64 + d];
        prA[d] = g_prA[(bh * 8 + ch) * 64 + d];
        prB[d] = g_prB[(bh * 8 + ch) * 64 + d];
    }
    __syncthreads();

    // stage: 128 rows x 64 floats, coalesced float4 gather (all threads)
#pragma unroll
    for (int p = 0; p < 8; p++) {
        int idx = p * 256 + tid;
        int m = idx >> 4, f4 = idx & 15;
        *(float4*)&stage[m * 64 + f4 * 4] =
            *(const float4*)&g_Wh[(size_t)(b * NN + tpis[m]) * CC + hh * DD + f4 * 4];
    }
    __syncthreads();

    if (tid < 128) {
        // local prefix scans (serial chain only over FMA latency)
        int half = tid >> 6, d = tid & 63;
        const float* w = half ? wBs : wAs;
        float* loc = half ? locB : locA;
        float run = 0.f;
#pragma unroll 8
        for (int m = 0; m < 128; m++) {
            run = fmaf(w[m], stage[m * 64 + d], run);
            loc[m * 64 + d] = run;
        }
    } else {
        // parallel query-metadata gather (high MLP, no serial chain)
        int t2 = tid - 128;
        for (int q = qs + t2; q < qe; q += 128) {
            int i = g_qord[base + q];
            int c = g_ci[base + i];
            int off = c - ch * 128 - 1;        // -1 only for bucket-0 (ch==0)
            qpk[q - qs] = i | ((off + 1) << 16);
            qes[q - qs]   = g_es[base + i];
            qes01[q - qs] = g_es01[base + i];
        }
    }
    __syncthreads();

    // serve queries from smem only
    {
        int qg = tid >> 6, d = tid & 63;
        for (int q = qg; q < nq; q += 4) {
            int pk = qpk[q];
            int i = pk & 0xFFFF;
            int offp = pk >> 16;               // 0 => bucket-0, else off+1
            float es = qes[q];
            float val;
            if (offp == 0) {
                val = es * Tot[d];
            } else {
                int off = offp - 1;
                val = es * (Tot[d] - prA[d] - locA[off * 64 + d])
                    + qes01[q] * (prB[d] + locB[off * 64 + d]);
            }
            store_hilo((size_t)(b * NN + i) * CC + hh * DD + d, val);
        }
    }
}

// ---------------------------------------------------------------------------
// k5m: out = h' @ out_W + b via mma.sync bf16 hi/lo (3 MMAs, fp32 acc).
// ---------------------------------------------------------------------------
__global__ __launch_bounds__(256) void k5m(const float* __restrict__ ob,
                                           float* __restrict__ out) {
    __shared__ __align__(16) __nv_bfloat16 Ah[32][72];
    __shared__ __align__(16) __nv_bfloat16 Al[32][72];
    __shared__ __align__(16) __nv_bfloat16 Bh[64][72];
    __shared__ __align__(16) __nv_bfloat16 Bl[64][72];
    int tid = threadIdx.x, lane = tid & 31, w = tid >> 5;
    int mi = w & 1, nc = w >> 1;
    int r0 = blockIdx.x * 32;

    uint32_t aoff = (uint32_t)(((((lane >> 3) & 1) * 8 + (lane & 7)) + mi * 16) * 72
                               + (lane >> 4) * 8) * 2;
    uint32_t boff = (uint32_t)((lane & 15) * 72 + (lane >> 4) * 8) * 2
                    + (uint32_t)nc * 32;
    uint32_t aAh = smem_u32(Ah) + aoff;
    uint32_t aAl = smem_u32(Al) + aoff;
    uint32_t aBh = smem_u32(Bh) + boff;
    uint32_t aBl = smem_u32(Bl) + boff;

    float acc[2][4] = {};

    for (int kt = 0; kt < CC; kt += 64) {
        __syncthreads();
        {
            int row = tid >> 3, g = tid & 7;
            *(uint4*)&Ah[row][g*8] =
                *(const uint4*)&g_hpH[(size_t)(r0 + row) * CC + kt + g*8];
            *(uint4*)&Al[row][g*8] =
                *(const uint4*)&g_hpL[(size_t)(r0 + row) * CC + kt + g*8];
        }
#pragma unroll
        for (int p = 0; p < 2; p++) {
            int idx = p * 256 + tid;
            int row = idx >> 3, g = idx & 7;
            *(uint4*)&Bh[row][g*8] = *(const uint4*)&g_oWH[(size_t)(kt + row) * 64 + g*8];
            *(uint4*)&Bl[row][g*8] = *(const uint4*)&g_oWL[(size_t)(kt + row) * 64 + g*8];
        }
        __syncthreads();

#pragma unroll
        for (int kk = 0; kk < 4; kk++) {
            uint32_t ka = (uint32_t)(kk * 32);
            uint32_t kb = (uint32_t)(kk * 16 * 144);
            uint32_t ah0, ah1, ah2, ah3, al0, al1, al2, al3;
            uint32_t bh0, bh1, bh2, bh3, bl0, bl1, bl2, bl3;
            LDSM4(ah0, ah1, ah2, ah3, aAh + ka);
            LDSM4(al0, al1, al2, al3, aAl + ka);
            LDSM_T4(bh0, bh1, bh2, bh3, aBh + kb);
            LDSM_T4(bl0, bl1, bl2, bl3, aBl + kb);
            MMA16816(acc[0][0], acc[0][1], acc[0][2], acc[0][3],
                     ah0, ah1, ah2, ah3, bh0, bh1);
            MMA16816(acc[1][0], acc[1][1], acc[1][2], acc[1][3],
                     ah0, ah1, ah2, ah3, bh2, bh3);
            MMA16816(acc[0][0], acc[0][1], acc[0][2], acc[0][3],
                     ah0, ah1, ah2, ah3, bl0, bl1);
            MMA16816(acc[1][0], acc[1][1], acc[1][2], acc[1][3],
                     ah0, ah1, ah2, ah3, bl2, bl3);
            MMA16816(acc[0][0], acc[0][1], acc[0][2], acc[0][3],
                     al0, al1, al2, al3, bh0, bh1);
            MMA16816(acc[1][0], acc[1][1], acc[1][2], acc[1][3],
                     al0, al1, al2, al3, bh2, bh3);
        }
    }

    int gr = lane >> 2, c2 = (lane & 3) * 2;
    int row0 = r0 + mi * 16 + gr;
#pragma unroll
    for (int t = 0; t < 2; t++) {
        int col = nc * 16 + t * 8 + c2;
        float b0 = ob[col], b1 = ob[col + 1];
        float2 o0 = {acc[t][0] + b0, acc[t][1] + b1};
        float2 o1 = {acc[t][2] + b0, acc[t][3] + b1};
        *(float2*)&out[(size_t)row0 * DD + col] = o0;
        *(float2*)&out[(size_t)(row0 + 8) * DD + col] = o1;
    }
}

// ---------------------------------------------------------------------------
extern "C" void kernel_launch(void* const* d_in, const int* in_sizes, int n_in,
                              void* d_out, int out_size) {
    const float* h    = (const float*)d_in[0];
    const float* W    = (const float*)d_in[2];
    const float* a    = (const float*)d_in[3];
    const float* oW   = (const float*)d_in[4];
    const float* ob   = (const float*)d_in[5];
    float* out = (float*)d_out;

    cudaFuncSetAttribute(kS_all, cudaFuncAttributeMaxDynamicSharedMemorySize,
                         KS_SMEM);
    cudaFuncSetAttribute(kD_apply, cudaFuncAttributeMaxDynamicSharedMemorySize,
                         KD_SMEM);

    kW_conv<<<(CC*DD)/256, 256>>>(oW);
    k1x<<<dim3(HH, (BB*NN)/64), 256>>>(h, W, a);
    kS_all<<<BB*HH, 1024, KS_SMEM>>>();
    kD_apply<<<BB*HH*8, 256, KD_SMEM>>>();
    k5m<<<(BB*NN)/32, 256>>>(ob, out);
}